// round 7
// baseline (speedup 1.0000x reference)
#include <cuda_runtime.h>
#include <math.h>

#define NN 50000
#define NE 800000
#define FIN 11
#define NP 196  // ceil(NN/256)

// ---------------- scratch ----------------
__device__ float g_h[(size_t)NN * 512];
__device__ float g_x[(size_t)NN * 512];
__device__ float g_hfin[(size_t)NN * 128];
__device__ float g_asrc[NN * 4];
__device__ float g_adst[NN * 4];
__device__ int   g_deg[NN];
__device__ int   g_rowptr[NN + 1];
__device__ int   g_cursor[NN];
__device__ int   g_csrc[NE];
__device__ int   g_src[NE];
__device__ int   g_dst[NE];
__device__ int   g_part[NP];
__device__ float g_gsum[128];
__device__ int   g_is64;

// ---------------- dtype detection ----------------
__global__ void k_detect(const int* __restrict__ ei32) {
    __shared__ int nz;
    if (threadIdx.x == 0) nz = 0;
    __syncthreads();
    if (ei32[2 * threadIdx.x + 1] != 0) atomicOr(&nz, 1);
    __syncthreads();
    if (threadIdx.x == 0) g_is64 = nz ? 0 : 1;
}

// ---------------- graph prep ----------------
__global__ void k_init() {
    int i = blockIdx.x * blockDim.x + threadIdx.x;
    if (i < NN) g_deg[i] = 0;
    if (i < 128) g_gsum[i] = 0.f;
}

__global__ void k_prep(const void* __restrict__ ei) {
    int e = blockIdx.x * blockDim.x + threadIdx.x;
    if (e >= NE) return;
    int s, d;
    if (g_is64) {
        const long long* p = (const long long*)ei;
        s = (int)p[e];
        d = (int)p[NE + e];
    } else {
        const int* p = (const int*)ei;
        s = p[e];
        d = p[NE + e];
    }
    s = min(max(s, 0), NN - 1);
    d = min(max(d, 0), NN - 1);
    g_src[e] = s;
    g_dst[e] = d;
    atomicAdd(&g_deg[d], 1);
}

__global__ void k_scan1() {
    __shared__ int sh[256];
    int t = threadIdx.x;
    int i = blockIdx.x * 256 + t;
    sh[t] = (i < NN) ? g_deg[i] : 0;
    __syncthreads();
    for (int o = 128; o > 0; o >>= 1) {
        if (t < o) sh[t] += sh[t + o];
        __syncthreads();
    }
    if (t == 0) g_part[blockIdx.x] = sh[0];
}

__global__ void k_scan2() {
    __shared__ int sh[256];
    int t = threadIdx.x;
    int v = (t < NP) ? g_part[t] : 0;
    sh[t] = v;
    __syncthreads();
    for (int o = 1; o < 256; o <<= 1) {
        int u = (t >= o) ? sh[t - o] : 0;
        __syncthreads();
        sh[t] += u;
        __syncthreads();
    }
    if (t < NP) g_part[t] = sh[t] - v;
}

__global__ void k_scan3() {
    __shared__ int sh[256];
    int t = threadIdx.x;
    int i = blockIdx.x * 256 + t;
    int v = (i < NN) ? g_deg[i] : 0;
    sh[t] = v;
    __syncthreads();
    for (int o = 1; o < 256; o <<= 1) {
        int u = (t >= o) ? sh[t - o] : 0;
        __syncthreads();
        sh[t] += u;
        __syncthreads();
    }
    if (i < NN) {
        int val = g_part[blockIdx.x] + sh[t] - v;
        g_rowptr[i] = val;
        g_cursor[i] = val;
        if (i == NN - 1) g_rowptr[NN] = val + v;
    }
}

__global__ void k_scatter() {
    int e = blockIdx.x * blockDim.x + threadIdx.x;
    if (e >= NE) return;
    int d = g_dst[e];
    int pos = atomicAdd(&g_cursor[d], 1);
    g_csrc[pos] = g_src[e];
}

// ---------------- layer-1 GEMM (K=11) with fused alpha ----------------
__global__ void k_gemm_l1(const float* __restrict__ x, const float* __restrict__ W,
                          const float* __restrict__ as, const float* __restrict__ ad) {
    int n = blockIdx.x;
    int c = threadIdx.x;  // 512
    __shared__ float xs[FIN];
    __shared__ float h1[4], h2[4];
    if (c < FIN) xs[c] = x[n * FIN + c];
    if (c >= 32 && c < 36) { h1[c - 32] = 0.f; h2[c - 32] = 0.f; }
    __syncthreads();
    float acc = 0.f;
#pragma unroll
    for (int k = 0; k < FIN; k++) acc += xs[k] * W[k * 512 + c];
    g_h[(size_t)n * 512 + c] = acc;
    // fused alpha: per-head dot products
    float s1 = acc * as[c];
    float s2 = acc * ad[c];
    for (int o = 16; o > 0; o >>= 1) {
        s1 += __shfl_down_sync(0xffffffffu, s1, o);
        s2 += __shfl_down_sync(0xffffffffu, s2, o);
    }
    int lane = c & 31, warp = c >> 5, head = warp >> 2;
    if (lane == 0) {
        atomicAdd(&h1[head], s1);
        atomicAdd(&h2[head], s2);
    }
    __syncthreads();
    if (c < 4) {
        g_asrc[n * 4 + c] = h1[c];
        g_adst[n * 4 + c] = h2[c];
    }
}

// ---------------- fused segment softmax + aggregation ----------------
template <int H, bool ELU, bool FIN_OUT>
__global__ void k_agg(const float* __restrict__ bias) {
    const int CH = H * 128;
    int n = blockIdx.x;
    int tid = threadIdx.x;  // 128
    int beg = g_rowptr[n];
    int end = g_rowptr[n + 1];

    float adn[H];
#pragma unroll
    for (int hh = 0; hh < H; hh++) adn[hh] = g_adst[n * H + hh];

    __shared__ float red[128];
    __shared__ float smax[H];
    __shared__ float ssum[H];
    __shared__ int ssrc[128];
    __shared__ float wsh[H][128];

    float mloc[H];
#pragma unroll
    for (int hh = 0; hh < H; hh++) mloc[hh] = -INFINITY;
    for (int i = beg + tid; i < end; i += 128) {
        int s = g_csrc[i];
#pragma unroll
        for (int hh = 0; hh < H; hh++) {
            float v = g_asrc[s * H + hh] + adn[hh];
            v = fmaxf(v, 0.2f * v);
            mloc[hh] = fmaxf(mloc[hh], v);
        }
    }
#pragma unroll
    for (int hh = 0; hh < H; hh++) {
        red[tid] = mloc[hh];
        __syncthreads();
        for (int o = 64; o > 0; o >>= 1) {
            if (tid < o) red[tid] = fmaxf(red[tid], red[tid + o]);
            __syncthreads();
        }
        if (tid == 0) smax[hh] = red[0];
        __syncthreads();
    }

    float sloc[H];
#pragma unroll
    for (int hh = 0; hh < H; hh++) sloc[hh] = 0.f;
    for (int i = beg + tid; i < end; i += 128) {
        int s = g_csrc[i];
#pragma unroll
        for (int hh = 0; hh < H; hh++) {
            float v = g_asrc[s * H + hh] + adn[hh];
            v = fmaxf(v, 0.2f * v);
            sloc[hh] += __expf(v - smax[hh]);
        }
    }
#pragma unroll
    for (int hh = 0; hh < H; hh++) {
        red[tid] = sloc[hh];
        __syncthreads();
        for (int o = 64; o > 0; o >>= 1) {
            if (tid < o) red[tid] += red[tid + o];
            __syncthreads();
        }
        if (tid == 0) ssum[hh] = red[0];
        __syncthreads();
    }

    float acc[H];
#pragma unroll
    for (int hh = 0; hh < H; hh++) acc[hh] = 0.f;
    for (int tb = beg; tb < end; tb += 128) {
        int i = tb + tid;
        if (i < end) {
            int s = g_csrc[i];
            ssrc[tid] = s;
#pragma unroll
            for (int hh = 0; hh < H; hh++) {
                float v = g_asrc[s * H + hh] + adn[hh];
                v = fmaxf(v, 0.2f * v);
                wsh[hh][tid] = __expf(v - smax[hh]);
            }
        }
        __syncthreads();
        int cnt = min(128, end - tb);
        for (int j = 0; j < cnt; j++) {
            int s = ssrc[j];
            const float* hr = g_h + (size_t)s * CH;
#pragma unroll
            for (int hh = 0; hh < H; hh++) acc[hh] += wsh[hh][j] * hr[hh * 128 + tid];
        }
        __syncthreads();
    }

    float* out = FIN_OUT ? g_hfin : g_x;
#pragma unroll
    for (int hh = 0; hh < H; hh++) {
        float denom = ssum[hh];
        float val = (denom > 0.f) ? acc[hh] / denom : 0.f;
        val += bias[hh * 128 + tid];
        if (ELU) val = (val > 0.f) ? val : (__expf(val) - 1.f);
        out[(size_t)n * CH + hh * 128 + tid] = val;
    }
}

// ---------------- 3xTF32 GEMM v2: pre-split hi/lo, double-buffered, fused alpha ----------------
__device__ __forceinline__ unsigned f2tf(float x) {
    unsigned u;
    asm("cvt.rna.tf32.f32 %0, %1;" : "=r"(u) : "f"(x));
    return u;
}

__device__ __forceinline__ void mma_tf32(float* c, unsigned a0, unsigned a1, unsigned a2,
                                         unsigned a3, unsigned b0, unsigned b1) {
    asm volatile(
        "mma.sync.aligned.m16n8k8.row.col.f32.tf32.tf32.f32 "
        "{%0,%1,%2,%3}, {%4,%5,%6,%7}, {%8,%9}, {%0,%1,%2,%3};"
        : "+f"(c[0]), "+f"(c[1]), "+f"(c[2]), "+f"(c[3])
        : "r"(a0), "r"(a1), "r"(a2), "r"(a3), "r"(b0), "r"(b1));
}

#define BK 16
#define TSZ 2560  // 128*20 uints per tile buffer
#define GEMM_SMEM (8 * TSZ * 4 + 2 * 128 * 4)

__global__ __launch_bounds__(256) void k_tfgemm2(const float* __restrict__ B,
                                                 const float* __restrict__ as,
                                                 const float* __restrict__ ad, int M, int N,
                                                 int K, int hstride) {
    extern __shared__ unsigned dsm[];
    unsigned* Ah = dsm;              // [2][128][20]
    unsigned* Al = Ah + 2 * TSZ;
    unsigned* Bh = Al + 2 * TSZ;
    unsigned* Bl = Bh + 2 * TSZ;
    float* s1b = (float*)(Bl + 2 * TSZ);  // [128]
    float* s2b = s1b + 128;

    int tid = threadIdx.x;
    int bn = blockIdx.x, bm = blockIdx.y;
    int lane = tid & 31;
    int warp = tid >> 5;
    int gid = lane >> 2;
    int tq = lane & 3;
    int wm = (warp & 1) * 64;
    int wn = (warp >> 1) * 32;

    int rowA = tid >> 2;
    int colA = (tid & 3) * 4;
    int rowB = tid >> 5;
    int colB = (tid & 31) * 4;

    float acc[4][4][4];
#pragma unroll
    for (int i = 0; i < 4; i++)
#pragma unroll
        for (int j = 0; j < 4; j++)
#pragma unroll
            for (int r = 0; r < 4; r++) acc[i][j][r] = 0.f;

    int mrow0 = bm * 128 + rowA;
    int mrow1 = mrow0 + 64;
    bool v0 = mrow0 < M, v1 = mrow1 < M;
    int nT = K / BK;

    float4 a0, a1, b0, b1;
    // prologue: load tile 0
    a0 = v0 ? *(const float4*)(g_x + (size_t)mrow0 * K + colA) : make_float4(0, 0, 0, 0);
    a1 = v1 ? *(const float4*)(g_x + (size_t)mrow1 * K + colA) : make_float4(0, 0, 0, 0);
    b0 = *(const float4*)(B + (size_t)rowB * N + bn * 128 + colB);
    b1 = *(const float4*)(B + (size_t)(rowB + 8) * N + bn * 128 + colB);

#define SPLIT_STORE(buf)                                                               \
    do {                                                                               \
        unsigned* ah = Ah + (buf)*TSZ; unsigned* al = Al + (buf)*TSZ;                  \
        unsigned* bh_ = Bh + (buf)*TSZ; unsigned* bl_ = Bl + (buf)*TSZ;                \
        float va[4] = {a0.x, a0.y, a0.z, a0.w};                                        \
        float vb[4] = {a1.x, a1.y, a1.z, a1.w};                                        \
        float vc[4] = {b0.x, b0.y, b0.z, b0.w};                                        \
        float vd[4] = {b1.x, b1.y, b1.z, b1.w};                                        \
        _Pragma("unroll") for (int q = 0; q < 4; q++) {                                \
            unsigned h_ = f2tf(va[q]);                                                 \
            ah[rowA * 20 + colA + q] = h_;                                             \
            al[rowA * 20 + colA + q] = f2tf(va[q] - __uint_as_float(h_));              \
            h_ = f2tf(vb[q]);                                                          \
            ah[(rowA + 64) * 20 + colA + q] = h_;                                      \
            al[(rowA + 64) * 20 + colA + q] = f2tf(vb[q] - __uint_as_float(h_));       \
            h_ = f2tf(vc[q]);                                                          \
            bh_[(colB + q) * 20 + rowB] = h_;                                          \
            bl_[(colB + q) * 20 + rowB] = f2tf(vc[q] - __uint_as_float(h_));           \
            h_ = f2tf(vd[q]);                                                          \
            bh_[(colB + q) * 20 + rowB + 8] = h_;                                      \
            bl_[(colB + q) * 20 + rowB + 8] = f2tf(vd[q] - __uint_as_float(h_));       \
        }                                                                              \
    } while (0)

    SPLIT_STORE(0);

    for (int t = 0; t < nT; t++) {
        __syncthreads();
        int k1 = (t + 1) * BK;
        if (t + 1 < nT) {
            a0 = v0 ? *(const float4*)(g_x + (size_t)mrow0 * K + k1 + colA)
                    : make_float4(0, 0, 0, 0);
            a1 = v1 ? *(const float4*)(g_x + (size_t)mrow1 * K + k1 + colA)
                    : make_float4(0, 0, 0, 0);
            b0 = *(const float4*)(B + (size_t)(k1 + rowB) * N + bn * 128 + colB);
            b1 = *(const float4*)(B + (size_t)(k1 + rowB + 8) * N + bn * 128 + colB);
        }
        int buf = t & 1;
        unsigned* ah = Ah + buf * TSZ;
        unsigned* al = Al + buf * TSZ;
        unsigned* bh_ = Bh + buf * TSZ;
        unsigned* bl_ = Bl + buf * TSZ;
#pragma unroll
        for (int kk = 0; kk < BK; kk += 8) {
            unsigned rah[4][4], ral[4][4], rbh[4][2], rbl[4][2];
#pragma unroll
            for (int mi = 0; mi < 4; mi++) {
                int mb = wm + mi * 16;
                rah[mi][0] = ah[(mb + gid) * 20 + kk + tq];
                rah[mi][1] = ah[(mb + gid + 8) * 20 + kk + tq];
                rah[mi][2] = ah[(mb + gid) * 20 + kk + tq + 4];
                rah[mi][3] = ah[(mb + gid + 8) * 20 + kk + tq + 4];
                ral[mi][0] = al[(mb + gid) * 20 + kk + tq];
                ral[mi][1] = al[(mb + gid + 8) * 20 + kk + tq];
                ral[mi][2] = al[(mb + gid) * 20 + kk + tq + 4];
                ral[mi][3] = al[(mb + gid + 8) * 20 + kk + tq + 4];
            }
#pragma unroll
            for (int ni = 0; ni < 4; ni++) {
                int nb = wn + ni * 8;
                rbh[ni][0] = bh_[(nb + gid) * 20 + kk + tq];
                rbh[ni][1] = bh_[(nb + gid) * 20 + kk + tq + 4];
                rbl[ni][0] = bl_[(nb + gid) * 20 + kk + tq];
                rbl[ni][1] = bl_[(nb + gid) * 20 + kk + tq + 4];
            }
#pragma unroll
            for (int mi = 0; mi < 4; mi++)
#pragma unroll
                for (int ni = 0; ni < 4; ni++) {
                    mma_tf32(acc[mi][ni], rah[mi][0], rah[mi][1], rah[mi][2], rah[mi][3],
                             rbh[ni][0], rbh[ni][1]);
                    mma_tf32(acc[mi][ni], rah[mi][0], rah[mi][1], rah[mi][2], rah[mi][3],
                             rbl[ni][0], rbl[ni][1]);
                    mma_tf32(acc[mi][ni], ral[mi][0], ral[mi][1], ral[mi][2], ral[mi][3],
                             rbh[ni][0], rbh[ni][1]);
                }
        }
        if (t + 1 < nT) {
            __syncthreads();
            int nbuf = (t + 1) & 1;
            SPLIT_STORE(nbuf);
        }
    }

    // epilogue: store h + fused alpha
    if (tid < 128) { s1b[tid] = 0.f; s2b[tid] = 0.f; }
    __syncthreads();
#pragma unroll
    for (int mi = 0; mi < 4; mi++) {
        int r0 = bm * 128 + wm + mi * 16 + gid;
        int r1 = r0 + 8;
        float p0 = 0.f, p1 = 0.f, q0 = 0.f, q1 = 0.f;
#pragma unroll
        for (int ni = 0; ni < 4; ni++) {
            int c = bn * 128 + wn + ni * 8 + tq * 2;
            if (r0 < M) {
                g_h[(size_t)r0 * N + c] = acc[mi][ni][0];
                g_h[(size_t)r0 * N + c + 1] = acc[mi][ni][1];
            }
            if (r1 < M) {
                g_h[(size_t)r1 * N + c] = acc[mi][ni][2];
                g_h[(size_t)r1 * N + c + 1] = acc[mi][ni][3];
            }
            float w0 = as[c], w1 = as[c + 1], u0 = ad[c], u1 = ad[c + 1];
            p0 += acc[mi][ni][0] * w0 + acc[mi][ni][1] * w1;
            q0 += acc[mi][ni][0] * u0 + acc[mi][ni][1] * u1;
            p1 += acc[mi][ni][2] * w0 + acc[mi][ni][3] * w1;
            q1 += acc[mi][ni][2] * u0 + acc[mi][ni][3] * u1;
        }
#pragma unroll
        for (int o = 1; o <= 2; o <<= 1) {
            p0 += __shfl_xor_sync(0xffffffffu, p0, o);
            q0 += __shfl_xor_sync(0xffffffffu, q0, o);
            p1 += __shfl_xor_sync(0xffffffffu, p1, o);
            q1 += __shfl_xor_sync(0xffffffffu, q1, o);
        }
        if (tq == 0) {
            int lr0 = wm + mi * 16 + gid;
            atomicAdd(&s1b[lr0], p0);
            atomicAdd(&s2b[lr0], q0);
            atomicAdd(&s1b[lr0 + 8], p1);
            atomicAdd(&s2b[lr0 + 8], q1);
        }
    }
    __syncthreads();
    if (tid < 128) {
        int r = bm * 128 + tid;
        if (r < M) {
            g_asrc[r * hstride + bn] = s1b[tid];
            g_adst[r * hstride + bn] = s2b[tid];
        }
    }
}

// ---------------- mean over nodes ----------------
__global__ void k_mean() {
    int c = threadIdx.x;
    int r0 = blockIdx.x * 128;
    int r1 = min(r0 + 128, NN);
    float s = 0.f;
    for (int r = r0; r < r1; r++) s += g_hfin[(size_t)r * 128 + c];
    atomicAdd(&g_gsum[c], s);
}

// ---------------- policy / value heads ----------------
__global__ void k_head(const int* __restrict__ cni, const float* __restrict__ pw1,
                       const float* __restrict__ pb1, const float* __restrict__ pw2,
                       const float* __restrict__ pb2, const float* __restrict__ vw1,
                       const float* __restrict__ vb1, const float* __restrict__ vw2,
                       const float* __restrict__ vb2, float* __restrict__ out) {
    __shared__ float comb[128], hid1[128], red[128];
    int t = threadIdx.x;
    int idx = cni[0];
    idx = min(max(idx, 0), NN - 1);
    comb[t] = g_gsum[t] * (1.0f / (float)NN) + g_hfin[(size_t)idx * 128 + t];
    __syncthreads();

    float a = 0.f;
    for (int c = 0; c < 128; c++) a += comb[c] * pw1[c * 128 + t];
    a += pb1[t];
    a = fmaxf(a, 0.f);
    hid1[t] = a;
    __syncthreads();
    if (t < 6) {
        float p = pb2[t];
        for (int j = 0; j < 128; j++) p += hid1[j] * pw2[j * 6 + t];
        out[t] = p;
    }
    __syncthreads();

    float b = 0.f;
    for (int c = 0; c < 128; c++) b += comb[c] * vw1[c * 128 + t];
    b += vb1[t];
    b = fmaxf(b, 0.f);
    red[t] = b * vw2[t];
    __syncthreads();
    for (int o = 64; o > 0; o >>= 1) {
        if (t < o) red[t] += red[t + o];
        __syncthreads();
    }
    if (t == 0) out[6] = red[0] + vb2[0];
}

// ---------------- driver ----------------
extern "C" void kernel_launch(void* const* d_in, const int* in_sizes, int n_in,
                              void* d_out, int out_size) {
    const float* x = (const float*)d_in[0];
    const void* ei = (const void*)d_in[1];
    const int* cni = (const int*)d_in[2];
    const float* W1 = (const float*)d_in[3];
    const float* as1 = (const float*)d_in[4];
    const float* ad1 = (const float*)d_in[5];
    const float* b1 = (const float*)d_in[6];
    const float* W2 = (const float*)d_in[7];
    const float* as2 = (const float*)d_in[8];
    const float* ad2 = (const float*)d_in[9];
    const float* b2 = (const float*)d_in[10];
    const float* W3 = (const float*)d_in[11];
    const float* as3 = (const float*)d_in[12];
    const float* ad3 = (const float*)d_in[13];
    const float* b3 = (const float*)d_in[14];
    const float* pw1 = (const float*)d_in[15];
    const float* pb1 = (const float*)d_in[16];
    const float* pw2 = (const float*)d_in[17];
    const float* pb2 = (const float*)d_in[18];
    const float* vw1 = (const float*)d_in[19];
    const float* vb1 = (const float*)d_in[20];
    const float* vw2 = (const float*)d_in[21];
    const float* vb2 = (const float*)d_in[22];
    float* out = (float*)d_out;

    cudaFuncSetAttribute(k_tfgemm2, cudaFuncAttributeMaxDynamicSharedMemorySize, GEMM_SMEM);

    // graph prep (CSR by dst)
    k_detect<<<1, 256>>>((const int*)ei);
    k_init<<<(NN + 255) / 256, 256>>>();
    k_prep<<<(NE + 255) / 256, 256>>>(ei);
    k_scan1<<<NP, 256>>>();
    k_scan2<<<1, 256>>>();
    k_scan3<<<NP, 256>>>();
    k_scatter<<<(NE + 255) / 256, 256>>>();

    // layer 1: 11 -> 4x128 (alpha fused)
    k_gemm_l1<<<NN, 512>>>(x, W1, as1, ad1);
    k_agg<4, true, false><<<NN, 128>>>(b1);

    // layer 2: 512 -> 4x128 (alpha fused into GEMM epilogue)
    {
        dim3 grid(4, (NN + 127) / 128);
        k_tfgemm2<<<grid, 256, GEMM_SMEM>>>(W2, as2, ad2, NN, 512, 512, 4);
    }
    k_agg<4, true, false><<<NN, 128>>>(b2);

    // layer 3: 512 -> 1x128
    {
        dim3 grid(1, (NN + 127) / 128);
        k_tfgemm2<<<grid, 256, GEMM_SMEM>>>(W3, as3, ad3, NN, 128, 512, 1);
    }
    k_agg<1, false, true><<<NN, 128>>>(b3);

    // readout + heads
    k_mean<<<(NN + 127) / 128, 128>>>();
    k_head<<<1, 128>>>(cni, pw1, pb1, pw2, pb2, vw1, vb1, vw2, vb2, out);
}

// round 11
// speedup vs baseline: 1.2235x; 1.2235x over previous
#include <cuda_runtime.h>
#include <math.h>

#define NN 50000
#define NE 800000
#define FIN 11
#define NP 196  // ceil(NN/256)

// ---------------- scratch ----------------
__device__ float g_h[(size_t)NN * 512];
__device__ float g_x[(size_t)NN * 512];
__device__ float g_hfin[(size_t)NN * 128];
__device__ float g_asrc[NN * 4];
__device__ float g_adst[NN * 4];
__device__ int   g_deg[NN];
__device__ int   g_rowptr[NN + 1];
__device__ int   g_cursor[NN];
__device__ int   g_csrc[NE];
__device__ int   g_src[NE];
__device__ int   g_dst[NE];
__device__ int   g_part[NP];
__device__ float g_gsum[128];
__device__ int   g_is64;

// ---------------- dtype detection ----------------
__global__ void k_detect(const int* __restrict__ ei32) {
    __shared__ int nz;
    if (threadIdx.x == 0) nz = 0;
    __syncthreads();
    if (ei32[2 * threadIdx.x + 1] != 0) atomicOr(&nz, 1);
    __syncthreads();
    if (threadIdx.x == 0) g_is64 = nz ? 0 : 1;
}

// ---------------- graph prep ----------------
__global__ void k_init() {
    int i = blockIdx.x * blockDim.x + threadIdx.x;
    if (i < NN) g_deg[i] = 0;
    if (i < 128) g_gsum[i] = 0.f;
}

__global__ void k_prep(const void* __restrict__ ei) {
    int e = blockIdx.x * blockDim.x + threadIdx.x;
    if (e >= NE) return;
    int s, d;
    if (g_is64) {
        const long long* p = (const long long*)ei;
        s = (int)p[e];
        d = (int)p[NE + e];
    } else {
        const int* p = (const int*)ei;
        s = p[e];
        d = p[NE + e];
    }
    s = min(max(s, 0), NN - 1);
    d = min(max(d, 0), NN - 1);
    g_src[e] = s;
    g_dst[e] = d;
    atomicAdd(&g_deg[d], 1);
}

__global__ void k_scan1() {
    __shared__ int sh[256];
    int t = threadIdx.x;
    int i = blockIdx.x * 256 + t;
    sh[t] = (i < NN) ? g_deg[i] : 0;
    __syncthreads();
    for (int o = 128; o > 0; o >>= 1) {
        if (t < o) sh[t] += sh[t + o];
        __syncthreads();
    }
    if (t == 0) g_part[blockIdx.x] = sh[0];
}

__global__ void k_scan2() {
    __shared__ int sh[256];
    int t = threadIdx.x;
    int v = (t < NP) ? g_part[t] : 0;
    sh[t] = v;
    __syncthreads();
    for (int o = 1; o < 256; o <<= 1) {
        int u = (t >= o) ? sh[t - o] : 0;
        __syncthreads();
        sh[t] += u;
        __syncthreads();
    }
    if (t < NP) g_part[t] = sh[t] - v;
}

__global__ void k_scan3() {
    __shared__ int sh[256];
    int t = threadIdx.x;
    int i = blockIdx.x * 256 + t;
    int v = (i < NN) ? g_deg[i] : 0;
    sh[t] = v;
    __syncthreads();
    for (int o = 1; o < 256; o <<= 1) {
        int u = (t >= o) ? sh[t - o] : 0;
        __syncthreads();
        sh[t] += u;
        __syncthreads();
    }
    if (i < NN) {
        int val = g_part[blockIdx.x] + sh[t] - v;
        g_rowptr[i] = val;
        g_cursor[i] = val;
        if (i == NN - 1) g_rowptr[NN] = val + v;
    }
}

__global__ void k_scatter() {
    int e = blockIdx.x * blockDim.x + threadIdx.x;
    if (e >= NE) return;
    int d = g_dst[e];
    int pos = atomicAdd(&g_cursor[d], 1);
    g_csrc[pos] = g_src[e];
}

// ---------------- layer-1 GEMM (K=11) tiled, fused alpha ----------------
#define L1N 32
__global__ __launch_bounds__(256) void k_gemm_l1(const float* __restrict__ x,
                                                 const float* __restrict__ W,
                                                 const float* __restrict__ as,
                                                 const float* __restrict__ ad) {
    __shared__ float Ws[FIN * 512];
    __shared__ float xs[L1N][FIN];
    __shared__ float ass[512], ads[512];
    int tid = threadIdx.x;
    int base = blockIdx.x * L1N;
    for (int i = tid; i < FIN * 512; i += 256) Ws[i] = W[i];
    for (int i = tid; i < 512; i += 256) { ass[i] = as[i]; ads[i] = ad[i]; }
    for (int i = tid; i < L1N * FIN; i += 256) {
        int nn = base + i / FIN;
        xs[i / FIN][i % FIN] = (nn < NN) ? x[nn * FIN + i % FIN] : 0.f;
    }
    __syncthreads();
    int warp = tid >> 5, lane = tid & 31;
#pragma unroll
    for (int u = 0; u < L1N / 8; u++) {
        int ln = u * 8 + warp;
        int n = base + ln;
        if (n >= NN) continue;
        float xr[FIN];
#pragma unroll
        for (int k = 0; k < FIN; k++) xr[k] = xs[ln][k];
        float s1[4] = {0, 0, 0, 0}, s2[4] = {0, 0, 0, 0};
#pragma unroll
        for (int j = 0; j < 16; j++) {
            int c = lane + 32 * j;
            float acc = 0.f;
#pragma unroll
            for (int k = 0; k < FIN; k++) acc += xr[k] * Ws[k * 512 + c];
            g_h[(size_t)n * 512 + c] = acc;
            int hh = j >> 2;
            s1[hh] += acc * ass[c];
            s2[hh] += acc * ads[c];
        }
#pragma unroll
        for (int hh = 0; hh < 4; hh++) {
            for (int o = 16; o > 0; o >>= 1) {
                s1[hh] += __shfl_down_sync(0xffffffffu, s1[hh], o);
                s2[hh] += __shfl_down_sync(0xffffffffu, s2[hh], o);
            }
        }
        if (lane == 0) {
#pragma unroll
            for (int hh = 0; hh < 4; hh++) {
                g_asrc[n * 4 + hh] = s1[hh];
                g_adst[n * 4 + hh] = s2[hh];
            }
        }
    }
}

// ---------------- fused segment softmax + aggregation (single-pass cached) ----------------
#define DM 512
template <int H, bool ELU, bool FIN_OUT>
__global__ void k_agg(const float* __restrict__ bias) {
    const int CH = H * 128;
    int n = blockIdx.x;
    int tid = threadIdx.x;  // 128
    int beg = g_rowptr[n];
    int end = g_rowptr[n + 1];
    int deg = end - beg;

    float adn[H];
#pragma unroll
    for (int hh = 0; hh < H; hh++) adn[hh] = g_adst[n * H + hh];

    __shared__ float red[128];
    __shared__ float smax[H];
    __shared__ float ssum[H];
    __shared__ int ssrc[DM];
    __shared__ float wsh[H][DM];

    float acc[H];
#pragma unroll
    for (int hh = 0; hh < H; hh++) acc[hh] = 0.f;

    if (deg <= DM) {
        // one pass: load src + logits
        for (int i = tid; i < deg; i += 128) {
            int s = g_csrc[beg + i];
            ssrc[i] = s;
#pragma unroll
            for (int hh = 0; hh < H; hh++) {
                float v = g_asrc[s * H + hh] + adn[hh];
                v = fmaxf(v, 0.2f * v);
                wsh[hh][i] = v;
            }
        }
        __syncthreads();
        // max per head
        float mloc[H];
#pragma unroll
        for (int hh = 0; hh < H; hh++) mloc[hh] = -INFINITY;
        for (int i = tid; i < deg; i += 128)
#pragma unroll
            for (int hh = 0; hh < H; hh++) mloc[hh] = fmaxf(mloc[hh], wsh[hh][i]);
#pragma unroll
        for (int hh = 0; hh < H; hh++) {
            red[tid] = mloc[hh];
            __syncthreads();
            for (int o = 64; o > 0; o >>= 1) {
                if (tid < o) red[tid] = fmaxf(red[tid], red[tid + o]);
                __syncthreads();
            }
            if (tid == 0) smax[hh] = red[0];
            __syncthreads();
        }
        // exp + sum (overwrite wsh with exp weights)
        float sloc[H];
#pragma unroll
        for (int hh = 0; hh < H; hh++) sloc[hh] = 0.f;
        for (int i = tid; i < deg; i += 128)
#pragma unroll
            for (int hh = 0; hh < H; hh++) {
                float w = __expf(wsh[hh][i] - smax[hh]);
                wsh[hh][i] = w;
                sloc[hh] += w;
            }
#pragma unroll
        for (int hh = 0; hh < H; hh++) {
            red[tid] = sloc[hh];
            __syncthreads();
            for (int o = 64; o > 0; o >>= 1) {
                if (tid < o) red[tid] += red[tid + o];
                __syncthreads();
            }
            if (tid == 0) ssum[hh] = red[0];
            __syncthreads();
        }
        // weighted gather
        for (int j = 0; j < deg; j++) {
            int s = ssrc[j];
            const float* hr = g_h + (size_t)s * CH;
#pragma unroll
            for (int hh = 0; hh < H; hh++) acc[hh] += wsh[hh][j] * hr[hh * 128 + tid];
        }
    } else {
        // fallback: 3-pass (uses first 128 slots of smem)
        float mloc[H];
#pragma unroll
        for (int hh = 0; hh < H; hh++) mloc[hh] = -INFINITY;
        for (int i = beg + tid; i < end; i += 128) {
            int s = g_csrc[i];
#pragma unroll
            for (int hh = 0; hh < H; hh++) {
                float v = g_asrc[s * H + hh] + adn[hh];
                v = fmaxf(v, 0.2f * v);
                mloc[hh] = fmaxf(mloc[hh], v);
            }
        }
#pragma unroll
        for (int hh = 0; hh < H; hh++) {
            red[tid] = mloc[hh];
            __syncthreads();
            for (int o = 64; o > 0; o >>= 1) {
                if (tid < o) red[tid] = fmaxf(red[tid], red[tid + o]);
                __syncthreads();
            }
            if (tid == 0) smax[hh] = red[0];
            __syncthreads();
        }
        float sloc[H];
#pragma unroll
        for (int hh = 0; hh < H; hh++) sloc[hh] = 0.f;
        for (int i = beg + tid; i < end; i += 128) {
            int s = g_csrc[i];
#pragma unroll
            for (int hh = 0; hh < H; hh++) {
                float v = g_asrc[s * H + hh] + adn[hh];
                v = fmaxf(v, 0.2f * v);
                sloc[hh] += __expf(v - smax[hh]);
            }
        }
#pragma unroll
        for (int hh = 0; hh < H; hh++) {
            red[tid] = sloc[hh];
            __syncthreads();
            for (int o = 64; o > 0; o >>= 1) {
                if (tid < o) red[tid] += red[tid + o];
                __syncthreads();
            }
            if (tid == 0) ssum[hh] = red[0];
            __syncthreads();
        }
        for (int tb = beg; tb < end; tb += 128) {
            int i = tb + tid;
            if (i < end) {
                int s = g_csrc[i];
                ssrc[tid] = s;
#pragma unroll
                for (int hh = 0; hh < H; hh++) {
                    float v = g_asrc[s * H + hh] + adn[hh];
                    v = fmaxf(v, 0.2f * v);
                    wsh[hh][tid] = __expf(v - smax[hh]);
                }
            }
            __syncthreads();
            int cnt = min(128, end - tb);
            for (int j = 0; j < cnt; j++) {
                int s = ssrc[j];
                const float* hr = g_h + (size_t)s * CH;
#pragma unroll
                for (int hh = 0; hh < H; hh++) acc[hh] += wsh[hh][j] * hr[hh * 128 + tid];
            }
            __syncthreads();
        }
    }

    float* out = FIN_OUT ? g_hfin : g_x;
#pragma unroll
    for (int hh = 0; hh < H; hh++) {
        float denom = ssum[hh];
        float val = (denom > 0.f) ? acc[hh] / denom : 0.f;
        val += bias[hh * 128 + tid];
        if (ELU) val = (val > 0.f) ? val : (__expf(val) - 1.f);
        out[(size_t)n * CH + hh * 128 + tid] = val;
    }
}

// ---------------- 3xTF32 tensor-core GEMM (v1 mainloop) + fused alpha ----------------
__device__ __forceinline__ unsigned f2tf(float x) {
    unsigned u;
    asm("cvt.rna.tf32.f32 %0, %1;" : "=r"(u) : "f"(x));
    return u;
}

__device__ __forceinline__ void mma_tf32(float* c, unsigned a0, unsigned a1, unsigned a2,
                                         unsigned a3, unsigned b0, unsigned b1) {
    asm volatile(
        "mma.sync.aligned.m16n8k8.row.col.f32.tf32.tf32.f32 "
        "{%0,%1,%2,%3}, {%4,%5,%6,%7}, {%8,%9}, {%0,%1,%2,%3};"
        : "+f"(c[0]), "+f"(c[1]), "+f"(c[2]), "+f"(c[3])
        : "r"(a0), "r"(a1), "r"(a2), "r"(a3), "r"(b0), "r"(b1));
}

#define BK 16
__global__ __launch_bounds__(256) void k_tfgemm(const float* __restrict__ B,
                                                const float* __restrict__ as,
                                                const float* __restrict__ ad, int M, int N,
                                                int K, int hstride) {
    __shared__ float As[128][20];
    __shared__ float Bs[128][20];
    __shared__ float s1b[128], s2b[128];
    int tid = threadIdx.x;
    int bn = blockIdx.x, bm = blockIdx.y;
    int lane = tid & 31;
    int warp = tid >> 5;
    int gid = lane >> 2;
    int tq = lane & 3;
    int wm = (warp & 1) * 64;
    int wn = (warp >> 1) * 32;

    int rowA = tid >> 2;
    int colA = (tid & 3) * 4;
    int rowB = tid >> 5;
    int colB = (tid & 31) * 4;

    float acc[4][4][4];
#pragma unroll
    for (int i = 0; i < 4; i++)
#pragma unroll
        for (int j = 0; j < 4; j++)
#pragma unroll
            for (int r = 0; r < 4; r++) acc[i][j][r] = 0.f;

    int mrow0 = bm * 128 + rowA;
    int mrow1 = mrow0 + 64;
    bool v0 = mrow0 < M, v1 = mrow1 < M;

    for (int k0 = 0; k0 < K; k0 += BK) {
        float4 a0 = v0 ? *(const float4*)(g_x + (size_t)mrow0 * K + k0 + colA)
                       : make_float4(0.f, 0.f, 0.f, 0.f);
        float4 a1 = v1 ? *(const float4*)(g_x + (size_t)mrow1 * K + k0 + colA)
                       : make_float4(0.f, 0.f, 0.f, 0.f);
        As[rowA][colA + 0] = a0.x; As[rowA][colA + 1] = a0.y;
        As[rowA][colA + 2] = a0.z; As[rowA][colA + 3] = a0.w;
        As[rowA + 64][colA + 0] = a1.x; As[rowA + 64][colA + 1] = a1.y;
        As[rowA + 64][colA + 2] = a1.z; As[rowA + 64][colA + 3] = a1.w;
        float4 b0 = *(const float4*)(B + (size_t)(k0 + rowB) * N + bn * 128 + colB);
        float4 b1 = *(const float4*)(B + (size_t)(k0 + rowB + 8) * N + bn * 128 + colB);
        Bs[colB + 0][rowB] = b0.x; Bs[colB + 1][rowB] = b0.y;
        Bs[colB + 2][rowB] = b0.z; Bs[colB + 3][rowB] = b0.w;
        Bs[colB + 0][rowB + 8] = b1.x; Bs[colB + 1][rowB + 8] = b1.y;
        Bs[colB + 2][rowB + 8] = b1.z; Bs[colB + 3][rowB + 8] = b1.w;
        __syncthreads();

#pragma unroll
        for (int kk = 0; kk < BK; kk += 8) {
            unsigned ah[4][4], al[4][4], bh[4][2], bl[4][2];
#pragma unroll
            for (int mi = 0; mi < 4; mi++) {
                int mb = wm + mi * 16;
                float f0 = As[mb + gid][kk + tq];
                float f1 = As[mb + gid + 8][kk + tq];
                float f2 = As[mb + gid][kk + tq + 4];
                float f3 = As[mb + gid + 8][kk + tq + 4];
                ah[mi][0] = f2tf(f0); al[mi][0] = f2tf(f0 - __uint_as_float(ah[mi][0]));
                ah[mi][1] = f2tf(f1); al[mi][1] = f2tf(f1 - __uint_as_float(ah[mi][1]));
                ah[mi][2] = f2tf(f2); al[mi][2] = f2tf(f2 - __uint_as_float(ah[mi][2]));
                ah[mi][3] = f2tf(f3); al[mi][3] = f2tf(f3 - __uint_as_float(ah[mi][3]));
            }
#pragma unroll
            for (int ni = 0; ni < 4; ni++) {
                int nb = wn + ni * 8;
                float f0 = Bs[nb + gid][kk + tq];
                float f1 = Bs[nb + gid][kk + tq + 4];
                bh[ni][0] = f2tf(f0); bl[ni][0] = f2tf(f0 - __uint_as_float(bh[ni][0]));
                bh[ni][1] = f2tf(f1); bl[ni][1] = f2tf(f1 - __uint_as_float(bh[ni][1]));
            }
#pragma unroll
            for (int mi = 0; mi < 4; mi++)
#pragma unroll
                for (int ni = 0; ni < 4; ni++) {
                    mma_tf32(acc[mi][ni], ah[mi][0], ah[mi][1], ah[mi][2], ah[mi][3],
                             bh[ni][0], bh[ni][1]);
                    mma_tf32(acc[mi][ni], ah[mi][0], ah[mi][1], ah[mi][2], ah[mi][3],
                             bl[ni][0], bl[ni][1]);
                    mma_tf32(acc[mi][ni], al[mi][0], al[mi][1], al[mi][2], al[mi][3],
                             bh[ni][0], bh[ni][1]);
                }
        }
        __syncthreads();
    }

    // epilogue: store h + fused alpha (this bn covers cols [bn*128, bn*128+128))
    if (tid < 128) { s1b[tid] = 0.f; s2b[tid] = 0.f; }
    __syncthreads();
#pragma unroll
    for (int mi = 0; mi < 4; mi++) {
        int r0 = bm * 128 + wm + mi * 16 + gid;
        int r1 = r0 + 8;
        float p0 = 0.f, p1 = 0.f, q0 = 0.f, q1 = 0.f;
#pragma unroll
        for (int ni = 0; ni < 4; ni++) {
            int c = bn * 128 + wn + ni * 8 + tq * 2;
            if (r0 < M) {
                g_h[(size_t)r0 * N + c] = acc[mi][ni][0];
                g_h[(size_t)r0 * N + c + 1] = acc[mi][ni][1];
            }
            if (r1 < M) {
                g_h[(size_t)r1 * N + c] = acc[mi][ni][2];
                g_h[(size_t)r1 * N + c + 1] = acc[mi][ni][3];
            }
            float w0 = as[c], w1 = as[c + 1], u0 = ad[c], u1 = ad[c + 1];
            p0 += acc[mi][ni][0] * w0 + acc[mi][ni][1] * w1;
            q0 += acc[mi][ni][0] * u0 + acc[mi][ni][1] * u1;
            p1 += acc[mi][ni][2] * w0 + acc[mi][ni][3] * w1;
            q1 += acc[mi][ni][2] * u0 + acc[mi][ni][3] * u1;
        }
#pragma unroll
        for (int o = 1; o <= 2; o <<= 1) {
            p0 += __shfl_xor_sync(0xffffffffu, p0, o);
            q0 += __shfl_xor_sync(0xffffffffu, q0, o);
            p1 += __shfl_xor_sync(0xffffffffu, p1, o);
            q1 += __shfl_xor_sync(0xffffffffu, q1, o);
        }
        if (tq == 0) {
            int lr0 = wm + mi * 16 + gid;
            atomicAdd(&s1b[lr0], p0);
            atomicAdd(&s2b[lr0], q0);
            atomicAdd(&s1b[lr0 + 8], p1);
            atomicAdd(&s2b[lr0 + 8], q1);
        }
    }
    __syncthreads();
    if (tid < 128) {
        int r = bm * 128 + tid;
        if (r < M) {
            g_asrc[r * hstride + bn] = s1b[tid];
            g_adst[r * hstride + bn] = s2b[tid];
        }
    }
}

// ---------------- mean over nodes ----------------
__global__ void k_mean() {
    int c = threadIdx.x;
    int r0 = blockIdx.x * 128;
    int r1 = min(r0 + 128, NN);
    float s = 0.f;
    for (int r = r0; r < r1; r++) s += g_hfin[(size_t)r * 128 + c];
    atomicAdd(&g_gsum[c], s);
}

// ---------------- policy / value heads ----------------
__global__ void k_head(const int* __restrict__ cni, const float* __restrict__ pw1,
                       const float* __restrict__ pb1, const float* __restrict__ pw2,
                       const float* __restrict__ pb2, const float* __restrict__ vw1,
                       const float* __restrict__ vb1, const float* __restrict__ vw2,
                       const float* __restrict__ vb2, float* __restrict__ out) {
    __shared__ float comb[128], hid1[128], red[128];
    int t = threadIdx.x;
    int idx = cni[0];
    idx = min(max(idx, 0), NN - 1);
    comb[t] = g_gsum[t] * (1.0f / (float)NN) + g_hfin[(size_t)idx * 128 + t];
    __syncthreads();

    float a = 0.f;
    for (int c = 0; c < 128; c++) a += comb[c] * pw1[c * 128 + t];
    a += pb1[t];
    a = fmaxf(a, 0.f);
    hid1[t] = a;
    __syncthreads();
    if (t < 6) {
        float p = pb2[t];
        for (int j = 0; j < 128; j++) p += hid1[j] * pw2[j * 6 + t];
        out[t] = p;
    }
    __syncthreads();

    float b = 0.f;
    for (int c = 0; c < 128; c++) b += comb[c] * vw1[c * 128 + t];
    b += vb1[t];
    b = fmaxf(b, 0.f);
    red[t] = b * vw2[t];
    __syncthreads();
    for (int o = 64; o > 0; o >>= 1) {
        if (t < o) red[t] += red[t + o];
        __syncthreads();
    }
    if (t == 0) out[6] = red[0] + vb2[0];
}

// ---------------- driver ----------------
extern "C" void kernel_launch(void* const* d_in, const int* in_sizes, int n_in,
                              void* d_out, int out_size) {
    const float* x = (const float*)d_in[0];
    const void* ei = (const void*)d_in[1];
    const int* cni = (const int*)d_in[2];
    const float* W1 = (const float*)d_in[3];
    const float* as1 = (const float*)d_in[4];
    const float* ad1 = (const float*)d_in[5];
    const float* b1 = (const float*)d_in[6];
    const float* W2 = (const float*)d_in[7];
    const float* as2 = (const float*)d_in[8];
    const float* ad2 = (const float*)d_in[9];
    const float* b2 = (const float*)d_in[10];
    const float* W3 = (const float*)d_in[11];
    const float* as3 = (const float*)d_in[12];
    const float* ad3 = (const float*)d_in[13];
    const float* b3 = (const float*)d_in[14];
    const float* pw1 = (const float*)d_in[15];
    const float* pb1 = (const float*)d_in[16];
    const float* pw2 = (const float*)d_in[17];
    const float* pb2 = (const float*)d_in[18];
    const float* vw1 = (const float*)d_in[19];
    const float* vb1 = (const float*)d_in[20];
    const float* vw2 = (const float*)d_in[21];
    const float* vb2 = (const float*)d_in[22];
    float* out = (float*)d_out;

    // graph prep (CSR by dst)
    k_detect<<<1, 256>>>((const int*)ei);
    k_init<<<(NN + 255) / 256, 256>>>();
    k_prep<<<(NE + 255) / 256, 256>>>(ei);
    k_scan1<<<NP, 256>>>();
    k_scan2<<<1, 256>>>();
    k_scan3<<<NP, 256>>>();
    k_scatter<<<(NE + 255) / 256, 256>>>();

    // layer 1: 11 -> 4x128 (alpha fused)
    k_gemm_l1<<<(NN + L1N - 1) / L1N, 256>>>(x, W1, as1, ad1);
    k_agg<4, true, false><<<NN, 128>>>(b1);

    // layer 2: 512 -> 4x128 (alpha fused into GEMM epilogue)
    {
        dim3 grid(4, (NN + 127) / 128);
        k_tfgemm<<<grid, 256>>>(W2, as2, ad2, NN, 512, 512, 4);
    }
    k_agg<4, true, false><<<NN, 128>>>(b2);

    // layer 3: 512 -> 1x128
    {
        dim3 grid(1, (NN + 127) / 128);
        k_tfgemm<<<grid, 256>>>(W3, as3, ad3, NN, 128, 512, 1);
    }
    k_agg<1, false, true><<<NN, 128>>>(b3);

    // readout + heads
    k_mean<<<(NN + 127) / 128, 128>>>();
    k_head<<<1, 128>>>(cni, pw1, pb1, pw2, pb2, vw1, vb1, vw2, vb2, out);
}

// round 13
// speedup vs baseline: 1.6459x; 1.3452x over previous
#include <cuda_runtime.h>
#include <cuda_bf16.h>
#include <math.h>

#define NN 50000
#define NE 800000
#define FIN 11
#define NP 196  // ceil(NN/256)

// ---------------- scratch ----------------
__device__ float g_h[(size_t)NN * 512];
__device__ __nv_bfloat16 g_xh[(size_t)NN * 512];  // hi plane of layer input
__device__ __nv_bfloat16 g_xl[(size_t)NN * 512];  // lo plane
__device__ __nv_bfloat16 g_w2h[512 * 512], g_w2l[512 * 512];  // W2^T split
__device__ __nv_bfloat16 g_w3h[128 * 512], g_w3l[128 * 512];  // W3^T split
__device__ float g_hfin[(size_t)NN * 128];
__device__ float g_asrc[NN * 4];
__device__ float g_adst[NN * 4];
__device__ int   g_deg[NN];
__device__ int   g_rowptr[NN + 1];
__device__ int   g_cursor[NN];
__device__ int   g_csrc[NE];
__device__ int   g_src[NE];
__device__ int   g_dst[NE];
__device__ int   g_part[NP];
__device__ float g_gsum[128];
__device__ int   g_is64;

// ---------------- dtype detection ----------------
__global__ void k_detect(const int* __restrict__ ei32) {
    __shared__ int nz;
    if (threadIdx.x == 0) nz = 0;
    __syncthreads();
    if (ei32[2 * threadIdx.x + 1] != 0) atomicOr(&nz, 1);
    __syncthreads();
    if (threadIdx.x == 0) g_is64 = nz ? 0 : 1;
}

// ---------------- graph prep ----------------
__global__ void k_init() {
    int i = blockIdx.x * blockDim.x + threadIdx.x;
    if (i < NN) g_deg[i] = 0;
    if (i < 128) g_gsum[i] = 0.f;
}

__global__ void k_prep(const void* __restrict__ ei) {
    int e = blockIdx.x * blockDim.x + threadIdx.x;
    if (e >= NE) return;
    int s, d;
    if (g_is64) {
        const long long* p = (const long long*)ei;
        s = (int)p[e];
        d = (int)p[NE + e];
    } else {
        const int* p = (const int*)ei;
        s = p[e];
        d = p[NE + e];
    }
    s = min(max(s, 0), NN - 1);
    d = min(max(d, 0), NN - 1);
    g_src[e] = s;
    g_dst[e] = d;
    atomicAdd(&g_deg[d], 1);
}

__global__ void k_scan1() {
    __shared__ int sh[256];
    int t = threadIdx.x;
    int i = blockIdx.x * 256 + t;
    sh[t] = (i < NN) ? g_deg[i] : 0;
    __syncthreads();
    for (int o = 128; o > 0; o >>= 1) {
        if (t < o) sh[t] += sh[t + o];
        __syncthreads();
    }
    if (t == 0) g_part[blockIdx.x] = sh[0];
}

__global__ void k_scan2() {
    __shared__ int sh[256];
    int t = threadIdx.x;
    int v = (t < NP) ? g_part[t] : 0;
    sh[t] = v;
    __syncthreads();
    for (int o = 1; o < 256; o <<= 1) {
        int u = (t >= o) ? sh[t - o] : 0;
        __syncthreads();
        sh[t] += u;
        __syncthreads();
    }
    if (t < NP) g_part[t] = sh[t] - v;
}

__global__ void k_scan3() {
    __shared__ int sh[256];
    int t = threadIdx.x;
    int i = blockIdx.x * 256 + t;
    int v = (i < NN) ? g_deg[i] : 0;
    sh[t] = v;
    __syncthreads();
    for (int o = 1; o < 256; o <<= 1) {
        int u = (t >= o) ? sh[t - o] : 0;
        __syncthreads();
        sh[t] += u;
        __syncthreads();
    }
    if (i < NN) {
        int val = g_part[blockIdx.x] + sh[t] - v;
        g_rowptr[i] = val;
        g_cursor[i] = val;
        if (i == NN - 1) g_rowptr[NN] = val + v;
    }
}

__global__ void k_scatter() {
    int e = blockIdx.x * blockDim.x + threadIdx.x;
    if (e >= NE) return;
    int d = g_dst[e];
    int pos = atomicAdd(&g_cursor[d], 1);
    g_csrc[pos] = g_src[e];
}

// ---------------- weight split kernels (write fixed device globals) ----------------
__global__ void k_wsplit2(const float* __restrict__ W) {
    int i = blockIdx.x * blockDim.x + threadIdx.x;  // i = n*512 + k, n<512
    if (i >= 512 * 512) return;
    int n = i >> 9, k = i & 511;
    float v = W[(size_t)k * 512 + n];
    __nv_bfloat16 hi = __float2bfloat16_rn(v);
    g_w2h[i] = hi;
    g_w2l[i] = __float2bfloat16_rn(v - __bfloat162float(hi));
}

__global__ void k_wsplit3(const float* __restrict__ W) {
    int i = blockIdx.x * blockDim.x + threadIdx.x;  // i = n*512 + k, n<128
    if (i >= 128 * 512) return;
    int n = i >> 9, k = i & 511;
    float v = W[(size_t)k * 128 + n];
    __nv_bfloat16 hi = __float2bfloat16_rn(v);
    g_w3h[i] = hi;
    g_w3l[i] = __float2bfloat16_rn(v - __bfloat162float(hi));
}

// ---------------- layer-1 GEMM (K=11) tiled, fused alpha ----------------
#define L1N 32
__global__ __launch_bounds__(256) void k_gemm_l1(const float* __restrict__ x,
                                                 const float* __restrict__ W,
                                                 const float* __restrict__ as,
                                                 const float* __restrict__ ad) {
    __shared__ float Ws[FIN * 512];
    __shared__ float xs[L1N][FIN];
    __shared__ float ass[512], ads[512];
    int tid = threadIdx.x;
    int base = blockIdx.x * L1N;
    for (int i = tid; i < FIN * 512; i += 256) Ws[i] = W[i];
    for (int i = tid; i < 512; i += 256) { ass[i] = as[i]; ads[i] = ad[i]; }
    for (int i = tid; i < L1N * FIN; i += 256) {
        int nn = base + i / FIN;
        xs[i / FIN][i % FIN] = (nn < NN) ? x[nn * FIN + i % FIN] : 0.f;
    }
    __syncthreads();
    int warp = tid >> 5, lane = tid & 31;
#pragma unroll
    for (int u = 0; u < L1N / 8; u++) {
        int ln = u * 8 + warp;
        int n = base + ln;
        if (n >= NN) continue;
        float xr[FIN];
#pragma unroll
        for (int k = 0; k < FIN; k++) xr[k] = xs[ln][k];
        float s1[4] = {0, 0, 0, 0}, s2[4] = {0, 0, 0, 0};
#pragma unroll
        for (int j = 0; j < 16; j++) {
            int c = lane + 32 * j;
            float acc = 0.f;
#pragma unroll
            for (int k = 0; k < FIN; k++) acc += xr[k] * Ws[k * 512 + c];
            g_h[(size_t)n * 512 + c] = acc;
            int hh = j >> 2;
            s1[hh] += acc * ass[c];
            s2[hh] += acc * ads[c];
        }
#pragma unroll
        for (int hh = 0; hh < 4; hh++) {
            for (int o = 16; o > 0; o >>= 1) {
                s1[hh] += __shfl_down_sync(0xffffffffu, s1[hh], o);
                s2[hh] += __shfl_down_sync(0xffffffffu, s2[hh], o);
            }
        }
        if (lane == 0) {
#pragma unroll
            for (int hh = 0; hh < 4; hh++) {
                g_asrc[n * 4 + hh] = s1[hh];
                g_adst[n * 4 + hh] = s2[hh];
            }
        }
    }
}

// ---------------- fused segment softmax + aggregation (single-pass cached) ----------------
// Output: FIN_OUT ? g_hfin (fp32) : split bf16 planes g_xh/g_xl.
#define DM 512
template <int H, bool ELU, bool FIN_OUT>
__global__ void k_agg(const float* __restrict__ bias) {
    const int CH = H * 128;
    int n = blockIdx.x;
    int tid = threadIdx.x;  // 128
    int beg = g_rowptr[n];
    int end = g_rowptr[n + 1];
    int deg = end - beg;

    float adn[H];
#pragma unroll
    for (int hh = 0; hh < H; hh++) adn[hh] = g_adst[n * H + hh];

    __shared__ float red[128];
    __shared__ float smax[H];
    __shared__ float ssum[H];
    __shared__ int ssrc[DM];
    __shared__ float wsh[H][DM];

    float acc[H];
#pragma unroll
    for (int hh = 0; hh < H; hh++) acc[hh] = 0.f;

    if (deg <= DM) {
        for (int i = tid; i < deg; i += 128) {
            int s = g_csrc[beg + i];
            ssrc[i] = s;
#pragma unroll
            for (int hh = 0; hh < H; hh++) {
                float v = g_asrc[s * H + hh] + adn[hh];
                v = fmaxf(v, 0.2f * v);
                wsh[hh][i] = v;
            }
        }
        __syncthreads();
        float mloc[H];
#pragma unroll
        for (int hh = 0; hh < H; hh++) mloc[hh] = -INFINITY;
        for (int i = tid; i < deg; i += 128)
#pragma unroll
            for (int hh = 0; hh < H; hh++) mloc[hh] = fmaxf(mloc[hh], wsh[hh][i]);
#pragma unroll
        for (int hh = 0; hh < H; hh++) {
            red[tid] = mloc[hh];
            __syncthreads();
            for (int o = 64; o > 0; o >>= 1) {
                if (tid < o) red[tid] = fmaxf(red[tid], red[tid + o]);
                __syncthreads();
            }
            if (tid == 0) smax[hh] = red[0];
            __syncthreads();
        }
        float sloc[H];
#pragma unroll
        for (int hh = 0; hh < H; hh++) sloc[hh] = 0.f;
        for (int i = tid; i < deg; i += 128)
#pragma unroll
            for (int hh = 0; hh < H; hh++) {
                float w = __expf(wsh[hh][i] - smax[hh]);
                wsh[hh][i] = w;
                sloc[hh] += w;
            }
#pragma unroll
        for (int hh = 0; hh < H; hh++) {
            red[tid] = sloc[hh];
            __syncthreads();
            for (int o = 64; o > 0; o >>= 1) {
                if (tid < o) red[tid] += red[tid + o];
                __syncthreads();
            }
            if (tid == 0) ssum[hh] = red[0];
            __syncthreads();
        }
        for (int j = 0; j < deg; j++) {
            int s = ssrc[j];
            const float* hr = g_h + (size_t)s * CH;
#pragma unroll
            for (int hh = 0; hh < H; hh++) acc[hh] += wsh[hh][j] * hr[hh * 128 + tid];
        }
    } else {
        float mloc[H];
#pragma unroll
        for (int hh = 0; hh < H; hh++) mloc[hh] = -INFINITY;
        for (int i = beg + tid; i < end; i += 128) {
            int s = g_csrc[i];
#pragma unroll
            for (int hh = 0; hh < H; hh++) {
                float v = g_asrc[s * H + hh] + adn[hh];
                v = fmaxf(v, 0.2f * v);
                mloc[hh] = fmaxf(mloc[hh], v);
            }
        }
#pragma unroll
        for (int hh = 0; hh < H; hh++) {
            red[tid] = mloc[hh];
            __syncthreads();
            for (int o = 64; o > 0; o >>= 1) {
                if (tid < o) red[tid] = fmaxf(red[tid], red[tid + o]);
                __syncthreads();
            }
            if (tid == 0) smax[hh] = red[0];
            __syncthreads();
        }
        float sloc[H];
#pragma unroll
        for (int hh = 0; hh < H; hh++) sloc[hh] = 0.f;
        for (int i = beg + tid; i < end; i += 128) {
            int s = g_csrc[i];
#pragma unroll
            for (int hh = 0; hh < H; hh++) {
                float v = g_asrc[s * H + hh] + adn[hh];
                v = fmaxf(v, 0.2f * v);
                sloc[hh] += __expf(v - smax[hh]);
            }
        }
#pragma unroll
        for (int hh = 0; hh < H; hh++) {
            red[tid] = sloc[hh];
            __syncthreads();
            for (int o = 64; o > 0; o >>= 1) {
                if (tid < o) red[tid] += red[tid + o];
                __syncthreads();
            }
            if (tid == 0) ssum[hh] = red[0];
            __syncthreads();
        }
        for (int tb = beg; tb < end; tb += 128) {
            int i = tb + tid;
            if (i < end) {
                int s = g_csrc[i];
                ssrc[tid] = s;
#pragma unroll
                for (int hh = 0; hh < H; hh++) {
                    float v = g_asrc[s * H + hh] + adn[hh];
                    v = fmaxf(v, 0.2f * v);
                    wsh[hh][tid] = __expf(v - smax[hh]);
                }
            }
            __syncthreads();
            int cnt = min(128, end - tb);
            for (int j = 0; j < cnt; j++) {
                int s = ssrc[j];
                const float* hr = g_h + (size_t)s * CH;
#pragma unroll
                for (int hh = 0; hh < H; hh++) acc[hh] += wsh[hh][j] * hr[hh * 128 + tid];
            }
            __syncthreads();
        }
    }

#pragma unroll
    for (int hh = 0; hh < H; hh++) {
        float denom = ssum[hh];
        float val = (denom > 0.f) ? acc[hh] / denom : 0.f;
        val += bias[hh * 128 + tid];
        if (ELU) val = (val > 0.f) ? val : (__expf(val) - 1.f);
        size_t idx = (size_t)n * CH + hh * 128 + tid;
        if (FIN_OUT) {
            g_hfin[idx] = val;
        } else {
            __nv_bfloat16 hi = __float2bfloat16_rn(val);
            g_xh[idx] = hi;
            g_xl[idx] = __float2bfloat16_rn(val - __bfloat162float(hi));
        }
    }
}

// ---------------- bf16 3-term tensor-core GEMM + fused alpha ----------------
__device__ __forceinline__ void mma_bf16(float* c, unsigned a0, unsigned a1, unsigned a2,
                                         unsigned a3, unsigned b0, unsigned b1) {
    asm volatile(
        "mma.sync.aligned.m16n8k16.row.col.f32.bf16.bf16.f32 "
        "{%0,%1,%2,%3}, {%4,%5,%6,%7}, {%8,%9}, {%0,%1,%2,%3};"
        : "+f"(c[0]), "+f"(c[1]), "+f"(c[2]), "+f"(c[3])
        : "r"(a0), "r"(a1), "r"(a2), "r"(a3), "r"(b0), "r"(b1));
}

#define BK 32
#define JP 20  // padded kpair stride : conflict-free frag LDS
// WSEL: 0 -> W2 planes (N=512), 1 -> W3 planes (N=128)
__global__ __launch_bounds__(256) void k_bfgemm(int wsel, const float* __restrict__ as,
                                                const float* __restrict__ ad, int M, int N,
                                                int K, int hstride) {
    const __nv_bfloat16* Bth = wsel ? g_w3h : g_w2h;
    const __nv_bfloat16* Btl = wsel ? g_w3l : g_w2l;

    __shared__ unsigned Ah[128][JP], Al[128][JP];
    __shared__ unsigned Bh[128][JP], Bl[128][JP];
    __shared__ float s1b[128], s2b[128];

    int tid = threadIdx.x;
    int bn = blockIdx.x, bm = blockIdx.y;
    int lane = tid & 31;
    int warp = tid >> 5;
    int gid = lane >> 2;
    int tq = lane & 3;
    int wm = (warp & 1) * 64;
    int wn = (warp >> 1) * 32;

    float acc[4][4][4];
#pragma unroll
    for (int i = 0; i < 4; i++)
#pragma unroll
        for (int j = 0; j < 4; j++)
#pragma unroll
            for (int r = 0; r < 4; r++) acc[i][j][r] = 0.f;

    int r0i = tid >> 1;       // row 0..127
    int jb0 = (tid & 1) * 8;  // kpair quad base (0 or 8)
    const uint4 z4 = make_uint4(0, 0, 0, 0);

    for (int k0 = 0; k0 < K; k0 += BK) {
        {
            int mrow = bm * 128 + r0i;
            bool v = mrow < M;
            const uint4* ph = (const uint4*)(g_xh + (size_t)mrow * K + k0 + jb0 * 2);
            const uint4* pl = (const uint4*)(g_xl + (size_t)mrow * K + k0 + jb0 * 2);
            uint4 h0 = v ? ph[0] : z4;
            uint4 h1 = v ? ph[1] : z4;
            uint4 l0 = v ? pl[0] : z4;
            uint4 l1 = v ? pl[1] : z4;
            *(uint4*)&Ah[r0i][jb0] = h0;
            *(uint4*)&Ah[r0i][jb0 + 4] = h1;
            *(uint4*)&Al[r0i][jb0] = l0;
            *(uint4*)&Al[r0i][jb0 + 4] = l1;
        }
        {
            int nrow = bn * 128 + r0i;
            const uint4* ph = (const uint4*)(Bth + (size_t)nrow * K + k0 + jb0 * 2);
            const uint4* pl = (const uint4*)(Btl + (size_t)nrow * K + k0 + jb0 * 2);
            uint4 h0 = ph[0];
            uint4 h1 = ph[1];
            uint4 l0 = pl[0];
            uint4 l1 = pl[1];
            *(uint4*)&Bh[r0i][jb0] = h0;
            *(uint4*)&Bh[r0i][jb0 + 4] = h1;
            *(uint4*)&Bl[r0i][jb0] = l0;
            *(uint4*)&Bl[r0i][jb0 + 4] = l1;
        }
        __syncthreads();

#pragma unroll
        for (int s = 0; s < 2; s++) {
            int jo = s * 8;
            unsigned rah[4][4], ral[4][4], rbh[4][2], rbl[4][2];
#pragma unroll
            for (int mi = 0; mi < 4; mi++) {
                int mb = wm + mi * 16;
                rah[mi][0] = Ah[mb + gid][jo + tq];
                rah[mi][1] = Ah[mb + gid + 8][jo + tq];
                rah[mi][2] = Ah[mb + gid][jo + tq + 4];
                rah[mi][3] = Ah[mb + gid + 8][jo + tq + 4];
                ral[mi][0] = Al[mb + gid][jo + tq];
                ral[mi][1] = Al[mb + gid + 8][jo + tq];
                ral[mi][2] = Al[mb + gid][jo + tq + 4];
                ral[mi][3] = Al[mb + gid + 8][jo + tq + 4];
            }
#pragma unroll
            for (int ni = 0; ni < 4; ni++) {
                int nb = wn + ni * 8;
                rbh[ni][0] = Bh[nb + gid][jo + tq];
                rbh[ni][1] = Bh[nb + gid][jo + tq + 4];
                rbl[ni][0] = Bl[nb + gid][jo + tq];
                rbl[ni][1] = Bl[nb + gid][jo + tq + 4];
            }
#pragma unroll
            for (int mi = 0; mi < 4; mi++)
#pragma unroll
                for (int ni = 0; ni < 4; ni++) {
                    mma_bf16(acc[mi][ni], rah[mi][0], rah[mi][1], rah[mi][2], rah[mi][3],
                             rbh[ni][0], rbh[ni][1]);
                    mma_bf16(acc[mi][ni], rah[mi][0], rah[mi][1], rah[mi][2], rah[mi][3],
                             rbl[ni][0], rbl[ni][1]);
                    mma_bf16(acc[mi][ni], ral[mi][0], ral[mi][1], ral[mi][2], ral[mi][3],
                             rbh[ni][0], rbh[ni][1]);
                }
        }
        __syncthreads();
    }

    // epilogue: store h + fused alpha
    if (tid < 128) { s1b[tid] = 0.f; s2b[tid] = 0.f; }
    __syncthreads();
#pragma unroll
    for (int mi = 0; mi < 4; mi++) {
        int r0 = bm * 128 + wm + mi * 16 + gid;
        int r1 = r0 + 8;
        float p0 = 0.f, p1 = 0.f, q0 = 0.f, q1 = 0.f;
#pragma unroll
        for (int ni = 0; ni < 4; ni++) {
            int c = bn * 128 + wn + ni * 8 + tq * 2;
            if (r0 < M) {
                g_h[(size_t)r0 * N + c] = acc[mi][ni][0];
                g_h[(size_t)r0 * N + c + 1] = acc[mi][ni][1];
            }
            if (r1 < M) {
                g_h[(size_t)r1 * N + c] = acc[mi][ni][2];
                g_h[(size_t)r1 * N + c + 1] = acc[mi][ni][3];
            }
            float w0 = as[c], w1 = as[c + 1], u0 = ad[c], u1 = ad[c + 1];
            p0 += acc[mi][ni][0] * w0 + acc[mi][ni][1] * w1;
            q0 += acc[mi][ni][0] * u0 + acc[mi][ni][1] * u1;
            p1 += acc[mi][ni][2] * w0 + acc[mi][ni][3] * w1;
            q1 += acc[mi][ni][2] * u0 + acc[mi][ni][3] * u1;
        }
#pragma unroll
        for (int o = 1; o <= 2; o <<= 1) {
            p0 += __shfl_xor_sync(0xffffffffu, p0, o);
            q0 += __shfl_xor_sync(0xffffffffu, q0, o);
            p1 += __shfl_xor_sync(0xffffffffu, p1, o);
            q1 += __shfl_xor_sync(0xffffffffu, q1, o);
        }
        if (tq == 0) {
            int lr0 = wm + mi * 16 + gid;
            atomicAdd(&s1b[lr0], p0);
            atomicAdd(&s2b[lr0], q0);
            atomicAdd(&s1b[lr0 + 8], p1);
            atomicAdd(&s2b[lr0 + 8], q1);
        }
    }
    __syncthreads();
    if (tid < 128) {
        int r = bm * 128 + tid;
        if (r < M) {
            g_asrc[r * hstride + bn] = s1b[tid];
            g_adst[r * hstride + bn] = s2b[tid];
        }
    }
}

// ---------------- mean over nodes ----------------
__global__ void k_mean() {
    int c = threadIdx.x;
    int r0 = blockIdx.x * 128;
    int r1 = min(r0 + 128, NN);
    float s = 0.f;
    for (int r = r0; r < r1; r++) s += g_hfin[(size_t)r * 128 + c];
    atomicAdd(&g_gsum[c], s);
}

// ---------------- policy / value heads ----------------
__global__ void k_head(const int* __restrict__ cni, const float* __restrict__ pw1,
                       const float* __restrict__ pb1, const float* __restrict__ pw2,
                       const float* __restrict__ pb2, const float* __restrict__ vw1,
                       const float* __restrict__ vb1, const float* __restrict__ vw2,
                       const float* __restrict__ vb2, float* __restrict__ out) {
    __shared__ float comb[128], hid1[128], red[128];
    int t = threadIdx.x;
    int idx = cni[0];
    idx = min(max(idx, 0), NN - 1);
    comb[t] = g_gsum[t] * (1.0f / (float)NN) + g_hfin[(size_t)idx * 128 + t];
    __syncthreads();

    float a = 0.f;
    for (int c = 0; c < 128; c++) a += comb[c] * pw1[c * 128 + t];
    a += pb1[t];
    a = fmaxf(a, 0.f);
    hid1[t] = a;
    __syncthreads();
    if (t < 6) {
        float p = pb2[t];
        for (int j = 0; j < 128; j++) p += hid1[j] * pw2[j * 6 + t];
        out[t] = p;
    }
    __syncthreads();

    float b = 0.f;
    for (int c = 0; c < 128; c++) b += comb[c] * vw1[c * 128 + t];
    b += vb1[t];
    b = fmaxf(b, 0.f);
    red[t] = b * vw2[t];
    __syncthreads();
    for (int o = 64; o > 0; o >>= 1) {
        if (t < o) red[t] += red[t + o];
        __syncthreads();
    }
    if (t == 0) out[6] = red[0] + vb2[0];
}

// ---------------- driver ----------------
extern "C" void kernel_launch(void* const* d_in, const int* in_sizes, int n_in,
                              void* d_out, int out_size) {
    const float* x = (const float*)d_in[0];
    const void* ei = (const void*)d_in[1];
    const int* cni = (const int*)d_in[2];
    const float* W1 = (const float*)d_in[3];
    const float* as1 = (const float*)d_in[4];
    const float* ad1 = (const float*)d_in[5];
    const float* b1 = (const float*)d_in[6];
    const float* W2 = (const float*)d_in[7];
    const float* as2 = (const float*)d_in[8];
    const float* ad2 = (const float*)d_in[9];
    const float* b2 = (const float*)d_in[10];
    const float* W3 = (const float*)d_in[11];
    const float* as3 = (const float*)d_in[12];
    const float* ad3 = (const float*)d_in[13];
    const float* b3 = (const float*)d_in[14];
    const float* pw1 = (const float*)d_in[15];
    const float* pb1 = (const float*)d_in[16];
    const float* pw2 = (const float*)d_in[17];
    const float* pb2 = (const float*)d_in[18];
    const float* vw1 = (const float*)d_in[19];
    const float* vb1 = (const float*)d_in[20];
    const float* vw2 = (const float*)d_in[21];
    const float* vb2 = (const float*)d_in[22];
    float* out = (float*)d_out;

    // graph prep (CSR by dst)
    k_detect<<<1, 256>>>((const int*)ei);
    k_init<<<(NN + 255) / 256, 256>>>();
    k_prep<<<(NE + 255) / 256, 256>>>(ei);
    k_scan1<<<NP, 256>>>();
    k_scan2<<<1, 256>>>();
    k_scan3<<<NP, 256>>>();
    k_scatter<<<(NE + 255) / 256, 256>>>();

    // weight splits (overlap with prep/agg on same stream order)
    k_wsplit2<<<(512 * 512 + 255) / 256, 256>>>(W2);
    k_wsplit3<<<(128 * 512 + 255) / 256, 256>>>(W3);

    // layer 1: 11 -> 4x128 (alpha fused)
    k_gemm_l1<<<(NN + L1N - 1) / L1N, 256>>>(x, W1, as1, ad1);
    k_agg<4, true, false><<<NN, 128>>>(b1);

    // layer 2: 512 -> 4x128 (bf16 split GEMM, alpha fused)
    {
        dim3 grid(4, (NN + 127) / 128);
        k_bfgemm<<<grid, 256>>>(0, as2, ad2, NN, 512, 512, 4);
    }
    k_agg<4, true, false><<<NN, 128>>>(b2);

    // layer 3: 512 -> 1x128
    {
        dim3 grid(1, (NN + 127) / 128);
        k_bfgemm<<<grid, 256>>>(1, as3, ad3, NN, 128, 512, 1);
    }
    k_agg<1, false, true><<<NN, 128>>>(b3);

    // readout + heads
    k_mean<<<(NN + 127) / 128, 128>>>();
    k_head<<<1, 128>>>(cni, pw1, pb1, pw2, pb2, vw1, vb1, vw2, vb2, out);
}

// round 14
// speedup vs baseline: 2.2374x; 1.3594x over previous
#include <cuda_runtime.h>
#include <cuda_bf16.h>
#include <math.h>

#define NN 50000
#define NE 800000
#define FIN 11
#define NP 196  // ceil(NN/256)

// ---------------- scratch ----------------
__device__ float g_h[(size_t)NN * 512];
__device__ __nv_bfloat16 g_xh[(size_t)NN * 512];
__device__ __nv_bfloat16 g_xl[(size_t)NN * 512];
__device__ __nv_bfloat16 g_w2h[512 * 512], g_w2l[512 * 512];
__device__ __nv_bfloat16 g_w3h[128 * 512], g_w3l[128 * 512];
__device__ float g_hfin[(size_t)NN * 128];
__device__ float g_asrc[NN * 4];
__device__ float g_adst[NN * 4];
__device__ int   g_deg[NN];
__device__ int   g_rowptr[NN + 1];
__device__ int   g_cursor[NN];
__device__ int   g_csrc[NE];
__device__ int   g_src[NE];
__device__ int   g_dst[NE];
__device__ int   g_part[NP];
__device__ float g_gsum[128];
__device__ int   g_is64;

// ---------------- dtype detection ----------------
__global__ void k_detect(const int* __restrict__ ei32) {
    __shared__ int nz;
    if (threadIdx.x == 0) nz = 0;
    __syncthreads();
    if (ei32[2 * threadIdx.x + 1] != 0) atomicOr(&nz, 1);
    __syncthreads();
    if (threadIdx.x == 0) g_is64 = nz ? 0 : 1;
}

// ---------------- graph prep ----------------
__global__ void k_init() {
    int i = blockIdx.x * blockDim.x + threadIdx.x;
    if (i < NN) g_deg[i] = 0;
    if (i < 128) g_gsum[i] = 0.f;
}

__global__ void k_prep(const void* __restrict__ ei) {
    int e = blockIdx.x * blockDim.x + threadIdx.x;
    if (e >= NE) return;
    int s, d;
    if (g_is64) {
        const long long* p = (const long long*)ei;
        s = (int)p[e];
        d = (int)p[NE + e];
    } else {
        const int* p = (const int*)ei;
        s = p[e];
        d = p[NE + e];
    }
    s = min(max(s, 0), NN - 1);
    d = min(max(d, 0), NN - 1);
    g_src[e] = s;
    g_dst[e] = d;
    atomicAdd(&g_deg[d], 1);
}

__global__ void k_scan1() {
    __shared__ int sh[256];
    int t = threadIdx.x;
    int i = blockIdx.x * 256 + t;
    sh[t] = (i < NN) ? g_deg[i] : 0;
    __syncthreads();
    for (int o = 128; o > 0; o >>= 1) {
        if (t < o) sh[t] += sh[t + o];
        __syncthreads();
    }
    if (t == 0) g_part[blockIdx.x] = sh[0];
}

__global__ void k_scan2() {
    __shared__ int sh[256];
    int t = threadIdx.x;
    int v = (t < NP) ? g_part[t] : 0;
    sh[t] = v;
    __syncthreads();
    for (int o = 1; o < 256; o <<= 1) {
        int u = (t >= o) ? sh[t - o] : 0;
        __syncthreads();
        sh[t] += u;
        __syncthreads();
    }
    if (t < NP) g_part[t] = sh[t] - v;
}

__global__ void k_scan3() {
    __shared__ int sh[256];
    int t = threadIdx.x;
    int i = blockIdx.x * 256 + t;
    int v = (i < NN) ? g_deg[i] : 0;
    sh[t] = v;
    __syncthreads();
    for (int o = 1; o < 256; o <<= 1) {
        int u = (t >= o) ? sh[t - o] : 0;
        __syncthreads();
        sh[t] += u;
        __syncthreads();
    }
    if (i < NN) {
        int val = g_part[blockIdx.x] + sh[t] - v;
        g_rowptr[i] = val;
        g_cursor[i] = val;
        if (i == NN - 1) g_rowptr[NN] = val + v;
    }
}

__global__ void k_scatter() {
    int e = blockIdx.x * blockDim.x + threadIdx.x;
    if (e >= NE) return;
    int d = g_dst[e];
    int pos = atomicAdd(&g_cursor[d], 1);
    g_csrc[pos] = g_src[e];
}

// ---------------- weight split kernels ----------------
__global__ void k_wsplit2(const float* __restrict__ W) {
    int i = blockIdx.x * blockDim.x + threadIdx.x;
    if (i >= 512 * 512) return;
    int n = i >> 9, k = i & 511;
    float v = W[(size_t)k * 512 + n];
    __nv_bfloat16 hi = __float2bfloat16_rn(v);
    g_w2h[i] = hi;
    g_w2l[i] = __float2bfloat16_rn(v - __bfloat162float(hi));
}

__global__ void k_wsplit3(const float* __restrict__ W) {
    int i = blockIdx.x * blockDim.x + threadIdx.x;
    if (i >= 128 * 512) return;
    int n = i >> 9, k = i & 511;
    float v = W[(size_t)k * 128 + n];
    __nv_bfloat16 hi = __float2bfloat16_rn(v);
    g_w3h[i] = hi;
    g_w3l[i] = __float2bfloat16_rn(v - __bfloat162float(hi));
}

// ---------------- layer-1 GEMM (K=11) tiled, fused alpha ----------------
#define L1N 32
__global__ __launch_bounds__(256) void k_gemm_l1(const float* __restrict__ x,
                                                 const float* __restrict__ W,
                                                 const float* __restrict__ as,
                                                 const float* __restrict__ ad) {
    __shared__ float Ws[FIN * 512];
    __shared__ float xs[L1N][FIN];
    __shared__ float ass[512], ads[512];
    int tid = threadIdx.x;
    int base = blockIdx.x * L1N;
    for (int i = tid; i < FIN * 512; i += 256) Ws[i] = W[i];
    for (int i = tid; i < 512; i += 256) { ass[i] = as[i]; ads[i] = ad[i]; }
    for (int i = tid; i < L1N * FIN; i += 256) {
        int nn = base + i / FIN;
        xs[i / FIN][i % FIN] = (nn < NN) ? x[nn * FIN + i % FIN] : 0.f;
    }
    __syncthreads();
    int warp = tid >> 5, lane = tid & 31;
#pragma unroll
    for (int u = 0; u < L1N / 8; u++) {
        int ln = u * 8 + warp;
        int n = base + ln;
        if (n >= NN) continue;
        float xr[FIN];
#pragma unroll
        for (int k = 0; k < FIN; k++) xr[k] = xs[ln][k];
        float s1[4] = {0, 0, 0, 0}, s2[4] = {0, 0, 0, 0};
#pragma unroll
        for (int j = 0; j < 16; j++) {
            int c = lane + 32 * j;
            float acc = 0.f;
#pragma unroll
            for (int k = 0; k < FIN; k++) acc += xr[k] * Ws[k * 512 + c];
            g_h[(size_t)n * 512 + c] = acc;
            int hh = j >> 2;
            s1[hh] += acc * ass[c];
            s2[hh] += acc * ads[c];
        }
#pragma unroll
        for (int hh = 0; hh < 4; hh++) {
            for (int o = 16; o > 0; o >>= 1) {
                s1[hh] += __shfl_down_sync(0xffffffffu, s1[hh], o);
                s2[hh] += __shfl_down_sync(0xffffffffu, s2[hh], o);
            }
        }
        if (lane == 0) {
#pragma unroll
            for (int hh = 0; hh < 4; hh++) {
                g_asrc[n * 4 + hh] = s1[hh];
                g_adst[n * 4 + hh] = s2[hh];
            }
        }
    }
}

// ---------------- H=4 agg: block/node, shfl reductions, float4 gather ----------------
#define DM 512
__device__ __forceinline__ float lrelu(float v) { return fmaxf(v, 0.2f * v); }

__global__ __launch_bounds__(128) void k_agg4(const float* __restrict__ bias) {
    int n = blockIdx.x;
    int tid = threadIdx.x;
    int lane = tid & 31, warp = tid >> 5;
    int beg = g_rowptr[n];
    int deg = g_rowptr[n + 1] - beg;

    float4 adv = *(const float4*)(g_adst + n * 4);
    float adn[4] = {adv.x, adv.y, adv.z, adv.w};

    __shared__ int ssrc[DM];
    __shared__ float wsh[4][DM];
    __shared__ float pmax[4][4], psum[4][4];

    if (deg <= DM) {
        float mloc[4] = {-INFINITY, -INFINITY, -INFINITY, -INFINITY};
        for (int i = tid; i < deg; i += 128) {
            int s = g_csrc[beg + i];
            ssrc[i] = s;
            float4 av = *(const float4*)(g_asrc + s * 4);
            float v0 = lrelu(av.x + adn[0]);
            float v1 = lrelu(av.y + adn[1]);
            float v2 = lrelu(av.z + adn[2]);
            float v3 = lrelu(av.w + adn[3]);
            wsh[0][i] = v0; wsh[1][i] = v1; wsh[2][i] = v2; wsh[3][i] = v3;
            mloc[0] = fmaxf(mloc[0], v0);
            mloc[1] = fmaxf(mloc[1], v1);
            mloc[2] = fmaxf(mloc[2], v2);
            mloc[3] = fmaxf(mloc[3], v3);
        }
#pragma unroll
        for (int hh = 0; hh < 4; hh++)
#pragma unroll
            for (int o = 16; o > 0; o >>= 1)
                mloc[hh] = fmaxf(mloc[hh], __shfl_xor_sync(0xffffffffu, mloc[hh], o));
        if (lane == 0)
#pragma unroll
            for (int hh = 0; hh < 4; hh++) pmax[warp][hh] = mloc[hh];
        __syncthreads();
        float gmax[4];
#pragma unroll
        for (int hh = 0; hh < 4; hh++)
            gmax[hh] = fmaxf(fmaxf(pmax[0][hh], pmax[1][hh]), fmaxf(pmax[2][hh], pmax[3][hh]));

        float sloc[4] = {0, 0, 0, 0};
        for (int i = tid; i < deg; i += 128) {
#pragma unroll
            for (int hh = 0; hh < 4; hh++) {
                float w = __expf(wsh[hh][i] - gmax[hh]);
                wsh[hh][i] = w;
                sloc[hh] += w;
            }
        }
#pragma unroll
        for (int hh = 0; hh < 4; hh++)
#pragma unroll
            for (int o = 16; o > 0; o >>= 1)
                sloc[hh] += __shfl_xor_sync(0xffffffffu, sloc[hh], o);
        if (lane == 0)
#pragma unroll
            for (int hh = 0; hh < 4; hh++) psum[warp][hh] = sloc[hh];
        __syncthreads();

        int head = warp;  // thread covers channels 4*tid..4*tid+3, all in head tid>>5
        float denom = psum[0][head] + psum[1][head] + psum[2][head] + psum[3][head];
        int c4 = tid * 4;
        float4 acc = make_float4(0.f, 0.f, 0.f, 0.f);
        for (int j = 0; j < deg; j++) {
            int s = ssrc[j];
            float w = wsh[head][j];
            float4 hv = *(const float4*)(g_h + (size_t)s * 512 + c4);
            acc.x += w * hv.x;
            acc.y += w * hv.y;
            acc.z += w * hv.z;
            acc.w += w * hv.w;
        }
        float inv = (denom > 0.f) ? 1.f / denom : 0.f;
        float4 bv = *(const float4*)(bias + c4);
        float vr[4] = {acc.x * inv + bv.x, acc.y * inv + bv.y, acc.z * inv + bv.z,
                       acc.w * inv + bv.w};
        size_t idx = (size_t)n * 512 + c4;
#pragma unroll
        for (int q = 0; q < 4; q++) {
            float val = vr[q];
            val = (val > 0.f) ? val : (__expf(val) - 1.f);
            __nv_bfloat16 hi = __float2bfloat16_rn(val);
            g_xh[idx + q] = hi;
            g_xl[idx + q] = __float2bfloat16_rn(val - __bfloat162float(hi));
        }
    } else {
        // fallback 3-pass streaming (rare hubs)
        __shared__ float red[128];
        __shared__ float smax[4], ssumh[4];
        int end = beg + deg;
        float mloc[4] = {-INFINITY, -INFINITY, -INFINITY, -INFINITY};
        for (int i = beg + tid; i < end; i += 128) {
            int s = g_csrc[i];
#pragma unroll
            for (int hh = 0; hh < 4; hh++)
                mloc[hh] = fmaxf(mloc[hh], lrelu(g_asrc[s * 4 + hh] + adn[hh]));
        }
#pragma unroll
        for (int hh = 0; hh < 4; hh++) {
            red[tid] = mloc[hh];
            __syncthreads();
            for (int o = 64; o > 0; o >>= 1) {
                if (tid < o) red[tid] = fmaxf(red[tid], red[tid + o]);
                __syncthreads();
            }
            if (tid == 0) smax[hh] = red[0];
            __syncthreads();
        }
        float sloc[4] = {0, 0, 0, 0};
        for (int i = beg + tid; i < end; i += 128) {
            int s = g_csrc[i];
#pragma unroll
            for (int hh = 0; hh < 4; hh++)
                sloc[hh] += __expf(lrelu(g_asrc[s * 4 + hh] + adn[hh]) - smax[hh]);
        }
#pragma unroll
        for (int hh = 0; hh < 4; hh++) {
            red[tid] = sloc[hh];
            __syncthreads();
            for (int o = 64; o > 0; o >>= 1) {
                if (tid < o) red[tid] += red[tid + o];
                __syncthreads();
            }
            if (tid == 0) ssumh[hh] = red[0];
            __syncthreads();
        }
        int head = warp;
        int c4 = tid * 4;
        float4 acc = make_float4(0.f, 0.f, 0.f, 0.f);
        for (int j = beg; j < end; j++) {
            int s = g_csrc[j];
            float w = __expf(lrelu(g_asrc[s * 4 + head] + adn[head]) - smax[head]);
            float4 hv = *(const float4*)(g_h + (size_t)s * 512 + c4);
            acc.x += w * hv.x;
            acc.y += w * hv.y;
            acc.z += w * hv.z;
            acc.w += w * hv.w;
        }
        float denom = ssumh[head];
        float inv = (denom > 0.f) ? 1.f / denom : 0.f;
        float4 bv = *(const float4*)(bias + c4);
        float vr[4] = {acc.x * inv + bv.x, acc.y * inv + bv.y, acc.z * inv + bv.z,
                       acc.w * inv + bv.w};
        size_t idx = (size_t)n * 512 + c4;
#pragma unroll
        for (int q = 0; q < 4; q++) {
            float val = vr[q];
            val = (val > 0.f) ? val : (__expf(val) - 1.f);
            __nv_bfloat16 hi = __float2bfloat16_rn(val);
            g_xh[idx + q] = hi;
            g_xl[idx + q] = __float2bfloat16_rn(val - __bfloat162float(hi));
        }
    }
}

// ---------------- H=1 agg: warp/node, no block barriers ----------------
__global__ __launch_bounds__(128) void k_agg1(const float* __restrict__ bias) {
    int warp = threadIdx.x >> 5, lane = threadIdx.x & 31;
    int n = blockIdx.x * 4 + warp;
    __shared__ int ssrcs[4][DM];
    __shared__ float wshs[4][DM];
    if (n >= NN) return;
    int* ssrc = ssrcs[warp];
    float* wsh = wshs[warp];
    int beg = g_rowptr[n];
    int deg = g_rowptr[n + 1] - beg;
    float adn = g_adst[n];

    if (deg <= DM) {
        float mloc = -INFINITY;
        for (int i = lane; i < deg; i += 32) {
            int s = g_csrc[beg + i];
            ssrc[i] = s;
            float v = lrelu(g_asrc[s] + adn);
            wsh[i] = v;
            mloc = fmaxf(mloc, v);
        }
#pragma unroll
        for (int o = 16; o > 0; o >>= 1)
            mloc = fmaxf(mloc, __shfl_xor_sync(0xffffffffu, mloc, o));
        float sloc = 0.f;
        for (int i = lane; i < deg; i += 32) {
            float w = __expf(wsh[i] - mloc);
            wsh[i] = w;
            sloc += w;
        }
#pragma unroll
        for (int o = 16; o > 0; o >>= 1) sloc += __shfl_xor_sync(0xffffffffu, sloc, o);
        __syncwarp();
        float4 acc = make_float4(0.f, 0.f, 0.f, 0.f);
        int c4 = lane * 4;
        for (int j = 0; j < deg; j++) {
            int s = ssrc[j];
            float w = wsh[j];
            float4 hv = *(const float4*)(g_h + (size_t)s * 128 + c4);
            acc.x += w * hv.x;
            acc.y += w * hv.y;
            acc.z += w * hv.z;
            acc.w += w * hv.w;
        }
        float inv = (sloc > 0.f) ? 1.f / sloc : 0.f;
        float4 bv = *(const float4*)(bias + c4);
        float4 outv = make_float4(acc.x * inv + bv.x, acc.y * inv + bv.y,
                                  acc.z * inv + bv.z, acc.w * inv + bv.w);
        *(float4*)(g_hfin + (size_t)n * 128 + c4) = outv;
    } else {
        // streaming 3-pass
        float mloc = -INFINITY;
        for (int i = lane; i < deg; i += 32)
            mloc = fmaxf(mloc, lrelu(g_asrc[g_csrc[beg + i]] + adn));
#pragma unroll
        for (int o = 16; o > 0; o >>= 1)
            mloc = fmaxf(mloc, __shfl_xor_sync(0xffffffffu, mloc, o));
        float sloc = 0.f;
        for (int i = lane; i < deg; i += 32)
            sloc += __expf(lrelu(g_asrc[g_csrc[beg + i]] + adn) - mloc);
#pragma unroll
        for (int o = 16; o > 0; o >>= 1) sloc += __shfl_xor_sync(0xffffffffu, sloc, o);
        float4 acc = make_float4(0.f, 0.f, 0.f, 0.f);
        int c4 = lane * 4;
        for (int j = 0; j < deg; j++) {
            int s = g_csrc[beg + j];
            float w = __expf(lrelu(g_asrc[s] + adn) - mloc);
            float4 hv = *(const float4*)(g_h + (size_t)s * 128 + c4);
            acc.x += w * hv.x;
            acc.y += w * hv.y;
            acc.z += w * hv.z;
            acc.w += w * hv.w;
        }
        float inv = (sloc > 0.f) ? 1.f / sloc : 0.f;
        float4 bv = *(const float4*)(bias + c4);
        float4 outv = make_float4(acc.x * inv + bv.x, acc.y * inv + bv.y,
                                  acc.z * inv + bv.z, acc.w * inv + bv.w);
        *(float4*)(g_hfin + (size_t)n * 128 + c4) = outv;
    }
}

// ---------------- bf16 3-term tensor-core GEMM + fused alpha ----------------
__device__ __forceinline__ void mma_bf16(float* c, unsigned a0, unsigned a1, unsigned a2,
                                         unsigned a3, unsigned b0, unsigned b1) {
    asm volatile(
        "mma.sync.aligned.m16n8k16.row.col.f32.bf16.bf16.f32 "
        "{%0,%1,%2,%3}, {%4,%5,%6,%7}, {%8,%9}, {%0,%1,%2,%3};"
        : "+f"(c[0]), "+f"(c[1]), "+f"(c[2]), "+f"(c[3])
        : "r"(a0), "r"(a1), "r"(a2), "r"(a3), "r"(b0), "r"(b1));
}

#define BK 32
#define JP 20
__global__ __launch_bounds__(256) void k_bfgemm(int wsel, const float* __restrict__ as,
                                                const float* __restrict__ ad, int M, int N,
                                                int K, int hstride) {
    const __nv_bfloat16* Bth = wsel ? g_w3h : g_w2h;
    const __nv_bfloat16* Btl = wsel ? g_w3l : g_w2l;

    __shared__ unsigned Ah[128][JP], Al[128][JP];
    __shared__ unsigned Bh[128][JP], Bl[128][JP];
    __shared__ float s1b[128], s2b[128];

    int tid = threadIdx.x;
    int bn = blockIdx.x, bm = blockIdx.y;
    int lane = tid & 31;
    int warp = tid >> 5;
    int gid = lane >> 2;
    int tq = lane & 3;
    int wm = (warp & 1) * 64;
    int wn = (warp >> 1) * 32;

    float acc[4][4][4];
#pragma unroll
    for (int i = 0; i < 4; i++)
#pragma unroll
        for (int j = 0; j < 4; j++)
#pragma unroll
            for (int r = 0; r < 4; r++) acc[i][j][r] = 0.f;

    int r0i = tid >> 1;
    int jb0 = (tid & 1) * 8;
    const uint4 z4 = make_uint4(0, 0, 0, 0);

    for (int k0 = 0; k0 < K; k0 += BK) {
        {
            int mrow = bm * 128 + r0i;
            bool v = mrow < M;
            const uint4* ph = (const uint4*)(g_xh + (size_t)mrow * K + k0 + jb0 * 2);
            const uint4* pl = (const uint4*)(g_xl + (size_t)mrow * K + k0 + jb0 * 2);
            uint4 h0 = v ? ph[0] : z4;
            uint4 h1 = v ? ph[1] : z4;
            uint4 l0 = v ? pl[0] : z4;
            uint4 l1 = v ? pl[1] : z4;
            *(uint4*)&Ah[r0i][jb0] = h0;
            *(uint4*)&Ah[r0i][jb0 + 4] = h1;
            *(uint4*)&Al[r0i][jb0] = l0;
            *(uint4*)&Al[r0i][jb0 + 4] = l1;
        }
        {
            int nrow = bn * 128 + r0i;
            const uint4* ph = (const uint4*)(Bth + (size_t)nrow * K + k0 + jb0 * 2);
            const uint4* pl = (const uint4*)(Btl + (size_t)nrow * K + k0 + jb0 * 2);
            uint4 h0 = ph[0];
            uint4 h1 = ph[1];
            uint4 l0 = pl[0];
            uint4 l1 = pl[1];
            *(uint4*)&Bh[r0i][jb0] = h0;
            *(uint4*)&Bh[r0i][jb0 + 4] = h1;
            *(uint4*)&Bl[r0i][jb0] = l0;
            *(uint4*)&Bl[r0i][jb0 + 4] = l1;
        }
        __syncthreads();

#pragma unroll
        for (int s = 0; s < 2; s++) {
            int jo = s * 8;
            unsigned rah[4][4], ral[4][4], rbh[4][2], rbl[4][2];
#pragma unroll
            for (int mi = 0; mi < 4; mi++) {
                int mb = wm + mi * 16;
                rah[mi][0] = Ah[mb + gid][jo + tq];
                rah[mi][1] = Ah[mb + gid + 8][jo + tq];
                rah[mi][2] = Ah[mb + gid][jo + tq + 4];
                rah[mi][3] = Ah[mb + gid + 8][jo + tq + 4];
                ral[mi][0] = Al[mb + gid][jo + tq];
                ral[mi][1] = Al[mb + gid + 8][jo + tq];
                ral[mi][2] = Al[mb + gid][jo + tq + 4];
                ral[mi][3] = Al[mb + gid + 8][jo + tq + 4];
            }
#pragma unroll
            for (int ni = 0; ni < 4; ni++) {
                int nb = wn + ni * 8;
                rbh[ni][0] = Bh[nb + gid][jo + tq];
                rbh[ni][1] = Bh[nb + gid][jo + tq + 4];
                rbl[ni][0] = Bl[nb + gid][jo + tq];
                rbl[ni][1] = Bl[nb + gid][jo + tq + 4];
            }
#pragma unroll
            for (int mi = 0; mi < 4; mi++)
#pragma unroll
                for (int ni = 0; ni < 4; ni++) {
                    mma_bf16(acc[mi][ni], rah[mi][0], rah[mi][1], rah[mi][2], rah[mi][3],
                             rbh[ni][0], rbh[ni][1]);
                    mma_bf16(acc[mi][ni], rah[mi][0], rah[mi][1], rah[mi][2], rah[mi][3],
                             rbl[ni][0], rbl[ni][1]);
                    mma_bf16(acc[mi][ni], ral[mi][0], ral[mi][1], ral[mi][2], ral[mi][3],
                             rbh[ni][0], rbh[ni][1]);
                }
        }
        __syncthreads();
    }

    if (tid < 128) { s1b[tid] = 0.f; s2b[tid] = 0.f; }
    __syncthreads();
#pragma unroll
    for (int mi = 0; mi < 4; mi++) {
        int r0 = bm * 128 + wm + mi * 16 + gid;
        int r1 = r0 + 8;
        float p0 = 0.f, p1 = 0.f, q0 = 0.f, q1 = 0.f;
#pragma unroll
        for (int ni = 0; ni < 4; ni++) {
            int c = bn * 128 + wn + ni * 8 + tq * 2;
            if (r0 < M) {
                g_h[(size_t)r0 * N + c] = acc[mi][ni][0];
                g_h[(size_t)r0 * N + c + 1] = acc[mi][ni][1];
            }
            if (r1 < M) {
                g_h[(size_t)r1 * N + c] = acc[mi][ni][2];
                g_h[(size_t)r1 * N + c + 1] = acc[mi][ni][3];
            }
            float w0 = as[c], w1 = as[c + 1], u0 = ad[c], u1 = ad[c + 1];
            p0 += acc[mi][ni][0] * w0 + acc[mi][ni][1] * w1;
            q0 += acc[mi][ni][0] * u0 + acc[mi][ni][1] * u1;
            p1 += acc[mi][ni][2] * w0 + acc[mi][ni][3] * w1;
            q1 += acc[mi][ni][2] * u0 + acc[mi][ni][3] * u1;
        }
#pragma unroll
        for (int o = 1; o <= 2; o <<= 1) {
            p0 += __shfl_xor_sync(0xffffffffu, p0, o);
            q0 += __shfl_xor_sync(0xffffffffu, q0, o);
            p1 += __shfl_xor_sync(0xffffffffu, p1, o);
            q1 += __shfl_xor_sync(0xffffffffu, q1, o);
        }
        if (tq == 0) {
            int lr0 = wm + mi * 16 + gid;
            atomicAdd(&s1b[lr0], p0);
            atomicAdd(&s2b[lr0], q0);
            atomicAdd(&s1b[lr0 + 8], p1);
            atomicAdd(&s2b[lr0 + 8], q1);
        }
    }
    __syncthreads();
    if (tid < 128) {
        int r = bm * 128 + tid;
        if (r < M) {
            g_asrc[r * hstride + bn] = s1b[tid];
            g_adst[r * hstride + bn] = s2b[tid];
        }
    }
}

// ---------------- mean over nodes ----------------
__global__ void k_mean() {
    int c = threadIdx.x;
    int r0 = blockIdx.x * 128;
    int r1 = min(r0 + 128, NN);
    float s = 0.f;
    for (int r = r0; r < r1; r++) s += g_hfin[(size_t)r * 128 + c];
    atomicAdd(&g_gsum[c], s);
}

// ---------------- policy / value heads ----------------
__global__ void k_head(const int* __restrict__ cni, const float* __restrict__ pw1,
                       const float* __restrict__ pb1, const float* __restrict__ pw2,
                       const float* __restrict__ pb2, const float* __restrict__ vw1,
                       const float* __restrict__ vb1, const float* __restrict__ vw2,
                       const float* __restrict__ vb2, float* __restrict__ out) {
    __shared__ float comb[128], hid1[128], red[128];
    int t = threadIdx.x;
    int idx = cni[0];
    idx = min(max(idx, 0), NN - 1);
    comb[t] = g_gsum[t] * (1.0f / (float)NN) + g_hfin[(size_t)idx * 128 + t];
    __syncthreads();

    float a = 0.f;
    for (int c = 0; c < 128; c++) a += comb[c] * pw1[c * 128 + t];
    a += pb1[t];
    a = fmaxf(a, 0.f);
    hid1[t] = a;
    __syncthreads();
    if (t < 6) {
        float p = pb2[t];
        for (int j = 0; j < 128; j++) p += hid1[j] * pw2[j * 6 + t];
        out[t] = p;
    }
    __syncthreads();

    float b = 0.f;
    for (int c = 0; c < 128; c++) b += comb[c] * vw1[c * 128 + t];
    b += vb1[t];
    b = fmaxf(b, 0.f);
    red[t] = b * vw2[t];
    __syncthreads();
    for (int o = 64; o > 0; o >>= 1) {
        if (t < o) red[t] += red[t + o];
        __syncthreads();
    }
    if (t == 0) out[6] = red[0] + vb2[0];
}

// ---------------- driver ----------------
extern "C" void kernel_launch(void* const* d_in, const int* in_sizes, int n_in,
                              void* d_out, int out_size) {
    const float* x = (const float*)d_in[0];
    const void* ei = (const void*)d_in[1];
    const int* cni = (const int*)d_in[2];
    const float* W1 = (const float*)d_in[3];
    const float* as1 = (const float*)d_in[4];
    const float* ad1 = (const float*)d_in[5];
    const float* b1 = (const float*)d_in[6];
    const float* W2 = (const float*)d_in[7];
    const float* as2 = (const float*)d_in[8];
    const float* ad2 = (const float*)d_in[9];
    const float* b2 = (const float*)d_in[10];
    const float* W3 = (const float*)d_in[11];
    const float* as3 = (const float*)d_in[12];
    const float* ad3 = (const float*)d_in[13];
    const float* b3 = (const float*)d_in[14];
    const float* pw1 = (const float*)d_in[15];
    const float* pb1 = (const float*)d_in[16];
    const float* pw2 = (const float*)d_in[17];
    const float* pb2 = (const float*)d_in[18];
    const float* vw1 = (const float*)d_in[19];
    const float* vb1 = (const float*)d_in[20];
    const float* vw2 = (const float*)d_in[21];
    const float* vb2 = (const float*)d_in[22];
    float* out = (float*)d_out;

    // graph prep (CSR by dst)
    k_detect<<<1, 256>>>((const int*)ei);
    k_init<<<(NN + 255) / 256, 256>>>();
    k_prep<<<(NE + 255) / 256, 256>>>(ei);
    k_scan1<<<NP, 256>>>();
    k_scan2<<<1, 256>>>();
    k_scan3<<<NP, 256>>>();
    k_scatter<<<(NE + 255) / 256, 256>>>();

    // weight splits
    k_wsplit2<<<(512 * 512 + 255) / 256, 256>>>(W2);
    k_wsplit3<<<(128 * 512 + 255) / 256, 256>>>(W3);

    // layer 1
    k_gemm_l1<<<(NN + L1N - 1) / L1N, 256>>>(x, W1, as1, ad1);
    k_agg4<<<NN, 128>>>(b1);

    // layer 2
    {
        dim3 grid(4, (NN + 127) / 128);
        k_bfgemm<<<grid, 256>>>(0, as2, ad2, NN, 512, 512, 4);
    }
    k_agg4<<<NN, 128>>>(b2);

    // layer 3
    {
        dim3 grid(1, (NN + 127) / 128);
        k_bfgemm<<<grid, 256>>>(1, as3, ad3, NN, 128, 512, 1);
    }
    k_agg1<<<(NN + 3) / 4, 128>>>(b3);

    // readout + heads
    k_mean<<<(NN + 127) / 128, 128>>>();
    k_head<<<1, 128>>>(cni, pw1, pb1, pw2, pb2, vw1, vb1, vw2, vb2, out);
}

// round 15
// speedup vs baseline: 2.4155x; 1.0796x over previous
#include <cuda_runtime.h>
#include <cuda_bf16.h>
#include <math.h>

#define NN 50000
#define NE 800000
#define FIN 11
#define NP 196  // ceil(NN/256)

// ---------------- scratch ----------------
__device__ float g_h[(size_t)NN * 512];
__device__ __nv_bfloat16 g_xh[(size_t)NN * 512];
__device__ __nv_bfloat16 g_xl[(size_t)NN * 512];
__device__ __nv_bfloat16 g_w2h[512 * 512], g_w2l[512 * 512];
__device__ __nv_bfloat16 g_w3h[128 * 512], g_w3l[128 * 512];
__device__ float g_hfin[(size_t)NN * 128];
__device__ float g_asrc[NN * 4];
__device__ float g_adst[NN * 4];
__device__ int   g_deg[NN];
__device__ int   g_rowptr[NN + 1];
__device__ int   g_cursor[NN];
__device__ int   g_csrc[NE];
__device__ int   g_src[NE];
__device__ int   g_dst[NE];
__device__ int   g_part[NP];
__device__ float g_gsum[128];
__device__ int   g_is64;

// ---------------- dtype detection ----------------
__global__ void k_detect(const int* __restrict__ ei32) {
    __shared__ int nz;
    if (threadIdx.x == 0) nz = 0;
    __syncthreads();
    if (ei32[2 * threadIdx.x + 1] != 0) atomicOr(&nz, 1);
    __syncthreads();
    if (threadIdx.x == 0) g_is64 = nz ? 0 : 1;
}

// ---------------- graph prep ----------------
__global__ void k_init() {
    int i = blockIdx.x * blockDim.x + threadIdx.x;
    if (i < NN) g_deg[i] = 0;
    if (i < 128) g_gsum[i] = 0.f;
}

__global__ void k_prep(const void* __restrict__ ei) {
    int e = blockIdx.x * blockDim.x + threadIdx.x;
    if (e >= NE) return;
    int s, d;
    if (g_is64) {
        const long long* p = (const long long*)ei;
        s = (int)p[e];
        d = (int)p[NE + e];
    } else {
        const int* p = (const int*)ei;
        s = p[e];
        d = p[NE + e];
    }
    s = min(max(s, 0), NN - 1);
    d = min(max(d, 0), NN - 1);
    g_src[e] = s;
    g_dst[e] = d;
    atomicAdd(&g_deg[d], 1);
}

__global__ void k_scan1() {
    __shared__ int sh[256];
    int t = threadIdx.x;
    int i = blockIdx.x * 256 + t;
    sh[t] = (i < NN) ? g_deg[i] : 0;
    __syncthreads();
    for (int o = 128; o > 0; o >>= 1) {
        if (t < o) sh[t] += sh[t + o];
        __syncthreads();
    }
    if (t == 0) g_part[blockIdx.x] = sh[0];
}

__global__ void k_scan2() {
    __shared__ int sh[256];
    int t = threadIdx.x;
    int v = (t < NP) ? g_part[t] : 0;
    sh[t] = v;
    __syncthreads();
    for (int o = 1; o < 256; o <<= 1) {
        int u = (t >= o) ? sh[t - o] : 0;
        __syncthreads();
        sh[t] += u;
        __syncthreads();
    }
    if (t < NP) g_part[t] = sh[t] - v;
}

__global__ void k_scan3() {
    __shared__ int sh[256];
    int t = threadIdx.x;
    int i = blockIdx.x * 256 + t;
    int v = (i < NN) ? g_deg[i] : 0;
    sh[t] = v;
    __syncthreads();
    for (int o = 1; o < 256; o <<= 1) {
        int u = (t >= o) ? sh[t - o] : 0;
        __syncthreads();
        sh[t] += u;
        __syncthreads();
    }
    if (i < NN) {
        int val = g_part[blockIdx.x] + sh[t] - v;
        g_rowptr[i] = val;
        g_cursor[i] = val;
        if (i == NN - 1) g_rowptr[NN] = val + v;
    }
}

__global__ void k_scatter() {
    int e = blockIdx.x * blockDim.x + threadIdx.x;
    if (e >= NE) return;
    int d = g_dst[e];
    int pos = atomicAdd(&g_cursor[d], 1);
    g_csrc[pos] = g_src[e];
}

// ---------------- weight split kernels ----------------
__global__ void k_wsplit2(const float* __restrict__ W) {
    int i = blockIdx.x * blockDim.x + threadIdx.x;
    if (i >= 512 * 512) return;
    int n = i >> 9, k = i & 511;
    float v = W[(size_t)k * 512 + n];
    __nv_bfloat16 hi = __float2bfloat16_rn(v);
    g_w2h[i] = hi;
    g_w2l[i] = __float2bfloat16_rn(v - __bfloat162float(hi));
}

__global__ void k_wsplit3(const float* __restrict__ W) {
    int i = blockIdx.x * blockDim.x + threadIdx.x;
    if (i >= 128 * 512) return;
    int n = i >> 9, k = i & 511;
    float v = W[(size_t)k * 128 + n];
    __nv_bfloat16 hi = __float2bfloat16_rn(v);
    g_w3h[i] = hi;
    g_w3l[i] = __float2bfloat16_rn(v - __bfloat162float(hi));
}

// ---------------- layer-1 GEMM (K=11) tiled, fused alpha ----------------
#define L1N 32
__global__ __launch_bounds__(256) void k_gemm_l1(const float* __restrict__ x,
                                                 const float* __restrict__ W,
                                                 const float* __restrict__ as,
                                                 const float* __restrict__ ad) {
    __shared__ float Ws[FIN * 512];
    __shared__ float xs[L1N][FIN];
    __shared__ float ass[512], ads[512];
    int tid = threadIdx.x;
    int base = blockIdx.x * L1N;
    for (int i = tid; i < FIN * 512; i += 256) Ws[i] = W[i];
    for (int i = tid; i < 512; i += 256) { ass[i] = as[i]; ads[i] = ad[i]; }
    for (int i = tid; i < L1N * FIN; i += 256) {
        int nn = base + i / FIN;
        xs[i / FIN][i % FIN] = (nn < NN) ? x[nn * FIN + i % FIN] : 0.f;
    }
    __syncthreads();
    int warp = tid >> 5, lane = tid & 31;
#pragma unroll
    for (int u = 0; u < L1N / 8; u++) {
        int ln = u * 8 + warp;
        int n = base + ln;
        if (n >= NN) continue;
        float xr[FIN];
#pragma unroll
        for (int k = 0; k < FIN; k++) xr[k] = xs[ln][k];
        float s1[4] = {0, 0, 0, 0}, s2[4] = {0, 0, 0, 0};
#pragma unroll
        for (int j = 0; j < 16; j++) {
            int c = lane + 32 * j;
            float acc = 0.f;
#pragma unroll
            for (int k = 0; k < FIN; k++) acc += xr[k] * Ws[k * 512 + c];
            g_h[(size_t)n * 512 + c] = acc;
            int hh = j >> 2;
            s1[hh] += acc * ass[c];
            s2[hh] += acc * ads[c];
        }
#pragma unroll
        for (int hh = 0; hh < 4; hh++) {
            for (int o = 16; o > 0; o >>= 1) {
                s1[hh] += __shfl_down_sync(0xffffffffu, s1[hh], o);
                s2[hh] += __shfl_down_sync(0xffffffffu, s2[hh], o);
            }
        }
        if (lane == 0) {
#pragma unroll
            for (int hh = 0; hh < 4; hh++) {
                g_asrc[n * 4 + hh] = s1[hh];
                g_adst[n * 4 + hh] = s2[hh];
            }
        }
    }
}

// ---------------- H=4 agg ----------------
#define DM 512
__device__ __forceinline__ float lrelu(float v) { return fmaxf(v, 0.2f * v); }

__global__ __launch_bounds__(128) void k_agg4(const float* __restrict__ bias) {
    int n = blockIdx.x;
    int tid = threadIdx.x;
    int lane = tid & 31, warp = tid >> 5;
    int beg = g_rowptr[n];
    int deg = g_rowptr[n + 1] - beg;

    float4 adv = *(const float4*)(g_adst + n * 4);
    float adn[4] = {adv.x, adv.y, adv.z, adv.w};

    __shared__ int ssrc[DM];
    __shared__ float wsh[4][DM];
    __shared__ float pmax[4][4], psum[4][4];

    if (deg <= DM) {
        float mloc[4] = {-INFINITY, -INFINITY, -INFINITY, -INFINITY};
        for (int i = tid; i < deg; i += 128) {
            int s = g_csrc[beg + i];
            ssrc[i] = s;
            float4 av = *(const float4*)(g_asrc + s * 4);
            float v0 = lrelu(av.x + adn[0]);
            float v1 = lrelu(av.y + adn[1]);
            float v2 = lrelu(av.z + adn[2]);
            float v3 = lrelu(av.w + adn[3]);
            wsh[0][i] = v0; wsh[1][i] = v1; wsh[2][i] = v2; wsh[3][i] = v3;
            mloc[0] = fmaxf(mloc[0], v0);
            mloc[1] = fmaxf(mloc[1], v1);
            mloc[2] = fmaxf(mloc[2], v2);
            mloc[3] = fmaxf(mloc[3], v3);
        }
#pragma unroll
        for (int hh = 0; hh < 4; hh++)
#pragma unroll
            for (int o = 16; o > 0; o >>= 1)
                mloc[hh] = fmaxf(mloc[hh], __shfl_xor_sync(0xffffffffu, mloc[hh], o));
        if (lane == 0)
#pragma unroll
            for (int hh = 0; hh < 4; hh++) pmax[warp][hh] = mloc[hh];
        __syncthreads();
        float gmax[4];
#pragma unroll
        for (int hh = 0; hh < 4; hh++)
            gmax[hh] = fmaxf(fmaxf(pmax[0][hh], pmax[1][hh]), fmaxf(pmax[2][hh], pmax[3][hh]));

        float sloc[4] = {0, 0, 0, 0};
        for (int i = tid; i < deg; i += 128) {
#pragma unroll
            for (int hh = 0; hh < 4; hh++) {
                float w = __expf(wsh[hh][i] - gmax[hh]);
                wsh[hh][i] = w;
                sloc[hh] += w;
            }
        }
#pragma unroll
        for (int hh = 0; hh < 4; hh++)
#pragma unroll
            for (int o = 16; o > 0; o >>= 1)
                sloc[hh] += __shfl_xor_sync(0xffffffffu, sloc[hh], o);
        if (lane == 0)
#pragma unroll
            for (int hh = 0; hh < 4; hh++) psum[warp][hh] = sloc[hh];
        __syncthreads();

        int head = warp;
        float denom = psum[0][head] + psum[1][head] + psum[2][head] + psum[3][head];
        int c4 = tid * 4;
        float4 acc = make_float4(0.f, 0.f, 0.f, 0.f);
        for (int j = 0; j < deg; j++) {
            int s = ssrc[j];
            float w = wsh[head][j];
            float4 hv = *(const float4*)(g_h + (size_t)s * 512 + c4);
            acc.x += w * hv.x;
            acc.y += w * hv.y;
            acc.z += w * hv.z;
            acc.w += w * hv.w;
        }
        float inv = (denom > 0.f) ? 1.f / denom : 0.f;
        float4 bv = *(const float4*)(bias + c4);
        float vr[4] = {acc.x * inv + bv.x, acc.y * inv + bv.y, acc.z * inv + bv.z,
                       acc.w * inv + bv.w};
        size_t idx = (size_t)n * 512 + c4;
#pragma unroll
        for (int q = 0; q < 4; q++) {
            float val = vr[q];
            val = (val > 0.f) ? val : (__expf(val) - 1.f);
            __nv_bfloat16 hi = __float2bfloat16_rn(val);
            g_xh[idx + q] = hi;
            g_xl[idx + q] = __float2bfloat16_rn(val - __bfloat162float(hi));
        }
    } else {
        __shared__ float red[128];
        __shared__ float smax[4], ssumh[4];
        int end = beg + deg;
        float mloc[4] = {-INFINITY, -INFINITY, -INFINITY, -INFINITY};
        for (int i = beg + tid; i < end; i += 128) {
            int s = g_csrc[i];
#pragma unroll
            for (int hh = 0; hh < 4; hh++)
                mloc[hh] = fmaxf(mloc[hh], lrelu(g_asrc[s * 4 + hh] + adn[hh]));
        }
#pragma unroll
        for (int hh = 0; hh < 4; hh++) {
            red[tid] = mloc[hh];
            __syncthreads();
            for (int o = 64; o > 0; o >>= 1) {
                if (tid < o) red[tid] = fmaxf(red[tid], red[tid + o]);
                __syncthreads();
            }
            if (tid == 0) smax[hh] = red[0];
            __syncthreads();
        }
        float sloc[4] = {0, 0, 0, 0};
        for (int i = beg + tid; i < end; i += 128) {
            int s = g_csrc[i];
#pragma unroll
            for (int hh = 0; hh < 4; hh++)
                sloc[hh] += __expf(lrelu(g_asrc[s * 4 + hh] + adn[hh]) - smax[hh]);
        }
#pragma unroll
        for (int hh = 0; hh < 4; hh++) {
            red[tid] = sloc[hh];
            __syncthreads();
            for (int o = 64; o > 0; o >>= 1) {
                if (tid < o) red[tid] += red[tid + o];
                __syncthreads();
            }
            if (tid == 0) ssumh[hh] = red[0];
            __syncthreads();
        }
        int head = warp;
        int c4 = tid * 4;
        float4 acc = make_float4(0.f, 0.f, 0.f, 0.f);
        for (int j = beg; j < end; j++) {
            int s = g_csrc[j];
            float w = __expf(lrelu(g_asrc[s * 4 + head] + adn[head]) - smax[head]);
            float4 hv = *(const float4*)(g_h + (size_t)s * 512 + c4);
            acc.x += w * hv.x;
            acc.y += w * hv.y;
            acc.z += w * hv.z;
            acc.w += w * hv.w;
        }
        float denom = ssumh[head];
        float inv = (denom > 0.f) ? 1.f / denom : 0.f;
        float4 bv = *(const float4*)(bias + c4);
        float vr[4] = {acc.x * inv + bv.x, acc.y * inv + bv.y, acc.z * inv + bv.z,
                       acc.w * inv + bv.w};
        size_t idx = (size_t)n * 512 + c4;
#pragma unroll
        for (int q = 0; q < 4; q++) {
            float val = vr[q];
            val = (val > 0.f) ? val : (__expf(val) - 1.f);
            __nv_bfloat16 hi = __float2bfloat16_rn(val);
            g_xh[idx + q] = hi;
            g_xl[idx + q] = __float2bfloat16_rn(val - __bfloat162float(hi));
        }
    }
}

// ---------------- H=1 agg: warp/node ----------------
__global__ __launch_bounds__(128) void k_agg1(const float* __restrict__ bias) {
    int warp = threadIdx.x >> 5, lane = threadIdx.x & 31;
    int n = blockIdx.x * 4 + warp;
    __shared__ int ssrcs[4][DM];
    __shared__ float wshs[4][DM];
    if (n >= NN) return;
    int* ssrc = ssrcs[warp];
    float* wsh = wshs[warp];
    int beg = g_rowptr[n];
    int deg = g_rowptr[n + 1] - beg;
    float adn = g_adst[n];

    if (deg <= DM) {
        float mloc = -INFINITY;
        for (int i = lane; i < deg; i += 32) {
            int s = g_csrc[beg + i];
            ssrc[i] = s;
            float v = lrelu(g_asrc[s] + adn);
            wsh[i] = v;
            mloc = fmaxf(mloc, v);
        }
#pragma unroll
        for (int o = 16; o > 0; o >>= 1)
            mloc = fmaxf(mloc, __shfl_xor_sync(0xffffffffu, mloc, o));
        float sloc = 0.f;
        for (int i = lane; i < deg; i += 32) {
            float w = __expf(wsh[i] - mloc);
            wsh[i] = w;
            sloc += w;
        }
#pragma unroll
        for (int o = 16; o > 0; o >>= 1) sloc += __shfl_xor_sync(0xffffffffu, sloc, o);
        __syncwarp();
        float4 acc = make_float4(0.f, 0.f, 0.f, 0.f);
        int c4 = lane * 4;
        for (int j = 0; j < deg; j++) {
            int s = ssrc[j];
            float w = wsh[j];
            float4 hv = *(const float4*)(g_h + (size_t)s * 128 + c4);
            acc.x += w * hv.x;
            acc.y += w * hv.y;
            acc.z += w * hv.z;
            acc.w += w * hv.w;
        }
        float inv = (sloc > 0.f) ? 1.f / sloc : 0.f;
        float4 bv = *(const float4*)(bias + c4);
        float4 outv = make_float4(acc.x * inv + bv.x, acc.y * inv + bv.y,
                                  acc.z * inv + bv.z, acc.w * inv + bv.w);
        *(float4*)(g_hfin + (size_t)n * 128 + c4) = outv;
    } else {
        float mloc = -INFINITY;
        for (int i = lane; i < deg; i += 32)
            mloc = fmaxf(mloc, lrelu(g_asrc[g_csrc[beg + i]] + adn));
#pragma unroll
        for (int o = 16; o > 0; o >>= 1)
            mloc = fmaxf(mloc, __shfl_xor_sync(0xffffffffu, mloc, o));
        float sloc = 0.f;
        for (int i = lane; i < deg; i += 32)
            sloc += __expf(lrelu(g_asrc[g_csrc[beg + i]] + adn) - mloc);
#pragma unroll
        for (int o = 16; o > 0; o >>= 1) sloc += __shfl_xor_sync(0xffffffffu, sloc, o);
        float4 acc = make_float4(0.f, 0.f, 0.f, 0.f);
        int c4 = lane * 4;
        for (int j = 0; j < deg; j++) {
            int s = g_csrc[beg + j];
            float w = __expf(lrelu(g_asrc[s] + adn) - mloc);
            float4 hv = *(const float4*)(g_h + (size_t)s * 128 + c4);
            acc.x += w * hv.x;
            acc.y += w * hv.y;
            acc.z += w * hv.z;
            acc.w += w * hv.w;
        }
        float inv = (sloc > 0.f) ? 1.f / sloc : 0.f;
        float4 bv = *(const float4*)(bias + c4);
        float4 outv = make_float4(acc.x * inv + bv.x, acc.y * inv + bv.y,
                                  acc.z * inv + bv.z, acc.w * inv + bv.w);
        *(float4*)(g_hfin + (size_t)n * 128 + c4) = outv;
    }
}

// ---------------- bf16 3-term GEMM, cp.async double-buffered ----------------
__device__ __forceinline__ void mma_bf16(float* c, unsigned a0, unsigned a1, unsigned a2,
                                         unsigned a3, unsigned b0, unsigned b1) {
    asm volatile(
        "mma.sync.aligned.m16n8k16.row.col.f32.bf16.bf16.f32 "
        "{%0,%1,%2,%3}, {%4,%5,%6,%7}, {%8,%9}, {%0,%1,%2,%3};"
        : "+f"(c[0]), "+f"(c[1]), "+f"(c[2]), "+f"(c[3])
        : "r"(a0), "r"(a1), "r"(a2), "r"(a3), "r"(b0), "r"(b1));
}

__device__ __forceinline__ void cp16(unsigned sm_addr, const void* g, int srcsz) {
    asm volatile("cp.async.cg.shared.global [%0], [%1], 16, %2;" ::"r"(sm_addr),
                 "l"(g), "r"(srcsz));
}

#define BK 32
#define JP 20
#define TPL (128 * JP)              // u32 per plane buffer
#define GSMEM (8 * TPL * 4)         // 81920 bytes dynamic

__global__ __launch_bounds__(256) void k_bfgemm(int wsel, const float* __restrict__ as,
                                                const float* __restrict__ ad, int M, int N,
                                                int K, int hstride) {
    const __nv_bfloat16* Bth = wsel ? g_w3h : g_w2h;
    const __nv_bfloat16* Btl = wsel ? g_w3l : g_w2l;

    extern __shared__ unsigned dsm[];
    unsigned* AhB = dsm;             // [2][TPL]
    unsigned* AlB = dsm + 2 * TPL;
    unsigned* BhB = dsm + 4 * TPL;
    unsigned* BlB = dsm + 6 * TPL;
    __shared__ float s1b[128], s2b[128];

    int tid = threadIdx.x;
    int bn = blockIdx.x, bm = blockIdx.y;
    int lane = tid & 31;
    int warp = tid >> 5;
    int gid = lane >> 2;
    int tq = lane & 3;
    int wm = (warp & 1) * 64;
    int wn = (warp >> 1) * 32;

    float acc[4][4][4];
#pragma unroll
    for (int i = 0; i < 4; i++)
#pragma unroll
        for (int j = 0; j < 4; j++)
#pragma unroll
            for (int r = 0; r < 4; r++) acc[i][j][r] = 0.f;

    int r0i = tid >> 1;
    int jb0 = (tid & 1) * 8;
    int mrow = bm * 128 + r0i;
    int asz = (mrow < M) ? 16 : 0;
    int nrow = bn * 128 + r0i;
    // element offsets (bf16): row*K + k0 + jb0*2 ; two uint4 = +0 and +8 elements
    const __nv_bfloat16* gA_h = g_xh + (size_t)mrow * K + jb0 * 2;
    const __nv_bfloat16* gA_l = g_xl + (size_t)mrow * K + jb0 * 2;
    const __nv_bfloat16* gB_h = Bth + (size_t)nrow * K + jb0 * 2;
    const __nv_bfloat16* gB_l = Btl + (size_t)nrow * K + jb0 * 2;
    unsigned smOff = (r0i * JP + jb0) * 4;  // byte offset within a plane buffer
    unsigned sAh = (unsigned)__cvta_generic_to_shared(AhB) + smOff;
    unsigned sAl = (unsigned)__cvta_generic_to_shared(AlB) + smOff;
    unsigned sBh = (unsigned)__cvta_generic_to_shared(BhB) + smOff;
    unsigned sBl = (unsigned)__cvta_generic_to_shared(BlB) + smOff;
    const unsigned bufB = TPL * 4;  // bytes per buffer

#define ISSUE(tk, buf)                                                        \
    do {                                                                      \
        int koff = (tk)*BK;                                                   \
        unsigned bo = (buf)*bufB;                                             \
        cp16(sAh + bo, gA_h + koff, asz);                                     \
        cp16(sAh + bo + 16, gA_h + koff + 8, asz);                            \
        cp16(sAl + bo, gA_l + koff, asz);                                     \
        cp16(sAl + bo + 16, gA_l + koff + 8, asz);                            \
        cp16(sBh + bo, gB_h + koff, 16);                                      \
        cp16(sBh + bo + 16, gB_h + koff + 8, 16);                             \
        cp16(sBl + bo, gB_l + koff, 16);                                      \
        cp16(sBl + bo + 16, gB_l + koff + 8, 16);                             \
        asm volatile("cp.async.commit_group;");                               \
    } while (0)

    int nT = K / BK;
    ISSUE(0, 0);

    for (int t = 0; t < nT; t++) {
        int buf = t & 1;
        if (t + 1 < nT) {
            ISSUE(t + 1, (t + 1) & 1);
            asm volatile("cp.async.wait_group 1;");
        } else {
            asm volatile("cp.async.wait_group 0;");
        }
        __syncthreads();
        unsigned* Ah = AhB + buf * TPL;
        unsigned* Al = AlB + buf * TPL;
        unsigned* Bh = BhB + buf * TPL;
        unsigned* Bl = BlB + buf * TPL;
#pragma unroll
        for (int s = 0; s < 2; s++) {
            int jo = s * 8;
            unsigned rah[4][4], ral[4][4], rbh[4][2], rbl[4][2];
#pragma unroll
            for (int mi = 0; mi < 4; mi++) {
                int mb = wm + mi * 16;
                rah[mi][0] = Ah[(mb + gid) * JP + jo + tq];
                rah[mi][1] = Ah[(mb + gid + 8) * JP + jo + tq];
                rah[mi][2] = Ah[(mb + gid) * JP + jo + tq + 4];
                rah[mi][3] = Ah[(mb + gid + 8) * JP + jo + tq + 4];
                ral[mi][0] = Al[(mb + gid) * JP + jo + tq];
                ral[mi][1] = Al[(mb + gid + 8) * JP + jo + tq];
                ral[mi][2] = Al[(mb + gid) * JP + jo + tq + 4];
                ral[mi][3] = Al[(mb + gid + 8) * JP + jo + tq + 4];
            }
#pragma unroll
            for (int ni = 0; ni < 4; ni++) {
                int nb = wn + ni * 8;
                rbh[ni][0] = Bh[(nb + gid) * JP + jo + tq];
                rbh[ni][1] = Bh[(nb + gid) * JP + jo + tq + 4];
                rbl[ni][0] = Bl[(nb + gid) * JP + jo + tq];
                rbl[ni][1] = Bl[(nb + gid) * JP + jo + tq + 4];
            }
#pragma unroll
            for (int mi = 0; mi < 4; mi++)
#pragma unroll
                for (int ni = 0; ni < 4; ni++) {
                    mma_bf16(acc[mi][ni], rah[mi][0], rah[mi][1], rah[mi][2], rah[mi][3],
                             rbh[ni][0], rbh[ni][1]);
                    mma_bf16(acc[mi][ni], rah[mi][0], rah[mi][1], rah[mi][2], rah[mi][3],
                             rbl[ni][0], rbl[ni][1]);
                    mma_bf16(acc[mi][ni], ral[mi][0], ral[mi][1], ral[mi][2], ral[mi][3],
                             rbh[ni][0], rbh[ni][1]);
                }
        }
        __syncthreads();
    }
#undef ISSUE

    // epilogue: store h + fused alpha
    if (tid < 128) { s1b[tid] = 0.f; s2b[tid] = 0.f; }
    __syncthreads();
#pragma unroll
    for (int mi = 0; mi < 4; mi++) {
        int r0 = bm * 128 + wm + mi * 16 + gid;
        int r1 = r0 + 8;
        float p0 = 0.f, p1 = 0.f, q0 = 0.f, q1 = 0.f;
#pragma unroll
        for (int ni = 0; ni < 4; ni++) {
            int c = bn * 128 + wn + ni * 8 + tq * 2;
            if (r0 < M) {
                g_h[(size_t)r0 * N + c] = acc[mi][ni][0];
                g_h[(size_t)r0 * N + c + 1] = acc[mi][ni][1];
            }
            if (r1 < M) {
                g_h[(size_t)r1 * N + c] = acc[mi][ni][2];
                g_h[(size_t)r1 * N + c + 1] = acc[mi][ni][3];
            }
            float w0 = as[c], w1 = as[c + 1], u0 = ad[c], u1 = ad[c + 1];
            p0 += acc[mi][ni][0] * w0 + acc[mi][ni][1] * w1;
            q0 += acc[mi][ni][0] * u0 + acc[mi][ni][1] * u1;
            p1 += acc[mi][ni][2] * w0 + acc[mi][ni][3] * w1;
            q1 += acc[mi][ni][2] * u0 + acc[mi][ni][3] * u1;
        }
#pragma unroll
        for (int o = 1; o <= 2; o <<= 1) {
            p0 += __shfl_xor_sync(0xffffffffu, p0, o);
            q0 += __shfl_xor_sync(0xffffffffu, q0, o);
            p1 += __shfl_xor_sync(0xffffffffu, p1, o);
            q1 += __shfl_xor_sync(0xffffffffu, q1, o);
        }
        if (tq == 0) {
            int lr0 = wm + mi * 16 + gid;
            atomicAdd(&s1b[lr0], p0);
            atomicAdd(&s2b[lr0], q0);
            atomicAdd(&s1b[lr0 + 8], p1);
            atomicAdd(&s2b[lr0 + 8], q1);
        }
    }
    __syncthreads();
    if (tid < 128) {
        int r = bm * 128 + tid;
        if (r < M) {
            g_asrc[r * hstride + bn] = s1b[tid];
            g_adst[r * hstride + bn] = s2b[tid];
        }
    }
}

// ---------------- mean over nodes ----------------
__global__ void k_mean() {
    int c = threadIdx.x;
    int r0 = blockIdx.x * 128;
    int r1 = min(r0 + 128, NN);
    float s = 0.f;
    for (int r = r0; r < r1; r++) s += g_hfin[(size_t)r * 128 + c];
    atomicAdd(&g_gsum[c], s);
}

// ---------------- policy / value heads ----------------
__global__ void k_head(const int* __restrict__ cni, const float* __restrict__ pw1,
                       const float* __restrict__ pb1, const float* __restrict__ pw2,
                       const float* __restrict__ pb2, const float* __restrict__ vw1,
                       const float* __restrict__ vb1, const float* __restrict__ vw2,
                       const float* __restrict__ vb2, float* __restrict__ out) {
    __shared__ float comb[128], hid1[128], red[128];
    int t = threadIdx.x;
    int idx = cni[0];
    idx = min(max(idx, 0), NN - 1);
    comb[t] = g_gsum[t] * (1.0f / (float)NN) + g_hfin[(size_t)idx * 128 + t];
    __syncthreads();

    float a = 0.f;
    for (int c = 0; c < 128; c++) a += comb[c] * pw1[c * 128 + t];
    a += pb1[t];
    a = fmaxf(a, 0.f);
    hid1[t] = a;
    __syncthreads();
    if (t < 6) {
        float p = pb2[t];
        for (int j = 0; j < 128; j++) p += hid1[j] * pw2[j * 6 + t];
        out[t] = p;
    }
    __syncthreads();

    float b = 0.f;
    for (int c = 0; c < 128; c++) b += comb[c] * vw1[c * 128 + t];
    b += vb1[t];
    b = fmaxf(b, 0.f);
    red[t] = b * vw2[t];
    __syncthreads();
    for (int o = 64; o > 0; o >>= 1) {
        if (t < o) red[t] += red[t + o];
        __syncthreads();
    }
    if (t == 0) out[6] = red[0] + vb2[0];
}

// ---------------- driver ----------------
extern "C" void kernel_launch(void* const* d_in, const int* in_sizes, int n_in,
                              void* d_out, int out_size) {
    const float* x = (const float*)d_in[0];
    const void* ei = (const void*)d_in[1];
    const int* cni = (const int*)d_in[2];
    const float* W1 = (const float*)d_in[3];
    const float* as1 = (const float*)d_in[4];
    const float* ad1 = (const float*)d_in[5];
    const float* b1 = (const float*)d_in[6];
    const float* W2 = (const float*)d_in[7];
    const float* as2 = (const float*)d_in[8];
    const float* ad2 = (const float*)d_in[9];
    const float* b2 = (const float*)d_in[10];
    const float* W3 = (const float*)d_in[11];
    const float* as3 = (const float*)d_in[12];
    const float* ad3 = (const float*)d_in[13];
    const float* b3 = (const float*)d_in[14];
    const float* pw1 = (const float*)d_in[15];
    const float* pb1 = (const float*)d_in[16];
    const float* pw2 = (const float*)d_in[17];
    const float* pb2 = (const float*)d_in[18];
    const float* vw1 = (const float*)d_in[19];
    const float* vb1 = (const float*)d_in[20];
    const float* vw2 = (const float*)d_in[21];
    const float* vb2 = (const float*)d_in[22];
    float* out = (float*)d_out;

    static bool attrSet = false;
    if (!attrSet) {
        cudaFuncSetAttribute(k_bfgemm, cudaFuncAttributeMaxDynamicSharedMemorySize,
                             GSMEM);
        attrSet = true;
    }

    // graph prep (CSR by dst)
    k_detect<<<1, 256>>>((const int*)ei);
    k_init<<<(NN + 255) / 256, 256>>>();
    k_prep<<<(NE + 255) / 256, 256>>>(ei);
    k_scan1<<<NP, 256>>>();
    k_scan2<<<1, 256>>>();
    k_scan3<<<NP, 256>>>();
    k_scatter<<<(NE + 255) / 256, 256>>>();

    // weight splits
    k_wsplit2<<<(512 * 512 + 255) / 256, 256>>>(W2);
    k_wsplit3<<<(128 * 512 + 255) / 256, 256>>>(W3);

    // layer 1
    k_gemm_l1<<<(NN + L1N - 1) / L1N, 256>>>(x, W1, as1, ad1);
    k_agg4<<<NN, 128>>>(b1);

    // layer 2
    {
        dim3 grid(4, (NN + 127) / 128);
        k_bfgemm<<<grid, 256, GSMEM>>>(0, as2, ad2, NN, 512, 512, 4);
    }
    k_agg4<<<NN, 128>>>(b2);

    // layer 3
    {
        dim3 grid(1, (NN + 127) / 128);
        k_bfgemm<<<grid, 256, GSMEM>>>(1, as3, ad3, NN, 128, 512, 1);
    }
    k_agg1<<<(NN + 3) / 4, 128>>>(b3);

    // readout + heads
    k_mean<<<(NN + 127) / 128, 128>>>();
    k_head<<<1, 128>>>(cni, pw1, pb1, pw2, pb2, vw1, vb1, vw2, vb2, out);
}